// round 1
// baseline (speedup 1.0000x reference)
#include <cuda_runtime.h>
#include <math.h>

#define D_MODEL 1024
#define NHEAD   16
#define DK      64
#define BATCH   2
#define SEQ     2048
#define MROWS   (BATCH*SEQ)   // 4096

// ---- scratch (device globals; no allocation allowed) ----
__device__ float g_Q[BATCH*NHEAD*SEQ*DK];   // [b][h][s][d]
__device__ float g_K[BATCH*NHEAD*SEQ*DK];
__device__ float g_V[BATCH*NHEAD*SEQ*DK];
__device__ float g_C[MROWS*D_MODEL];        // combined [b][s][h*64+d]

// ============================================================
// GEMM: out = A @ W^T + bias.  A: [4096,1024], W: [1024,1024] (row-major,
// torch Linear weight), bias: [1024].
// split==1: write into split-head layout [b][h][s][d]
// split==0: write row-major [m][n]
// Tiles: BM=BN=64, BK=16; 256 threads; 4x4 micro-tile per thread.
// ============================================================
#define BM 64
#define BN 64
#define BK 16
#define PADS 68   // smem row stride (floats) for [k][m] staging

__global__ __launch_bounds__(256) void gemm_xWT(
    const float* __restrict__ A, const float* __restrict__ W,
    const float* __restrict__ bias, float* __restrict__ out, int split)
{
    __shared__ float As[BK*PADS];
    __shared__ float Bs[BK*PADS];

    const int tid = threadIdx.x;
    const int tx = tid & 15;        // 0..15 -> 4 output cols each
    const int ty = tid >> 4;        // 0..15 -> 4 output rows each
    const int m0 = blockIdx.x * BM;
    const int n0 = blockIdx.y * BN;

    // loader mapping: each thread loads one float4 of A and one of W per k-step
    const int lr = tid >> 2;          // 0..63 row within tile
    const int lc = (tid & 3) * 4;     // 0,4,8,12 col within BK

    const float* Ald = A + (size_t)(m0 + lr) * D_MODEL + lc;
    const float* Wld = W + (size_t)(n0 + lr) * D_MODEL + lc;

    float acc[4][4] = {};

    for (int k0 = 0; k0 < D_MODEL; k0 += BK) {
        float4 a = *(const float4*)(Ald + k0);
        float4 b = *(const float4*)(Wld + k0);
        As[(lc+0)*PADS + lr] = a.x;  As[(lc+1)*PADS + lr] = a.y;
        As[(lc+2)*PADS + lr] = a.z;  As[(lc+3)*PADS + lr] = a.w;
        Bs[(lc+0)*PADS + lr] = b.x;  Bs[(lc+1)*PADS + lr] = b.y;
        Bs[(lc+2)*PADS + lr] = b.z;  Bs[(lc+3)*PADS + lr] = b.w;
        __syncthreads();

        #pragma unroll
        for (int k = 0; k < BK; ++k) {
            float4 av = *(const float4*)&As[k*PADS + 4*ty];
            float4 bv = *(const float4*)&Bs[k*PADS + 4*tx];
            float ar[4] = {av.x, av.y, av.z, av.w};
            float br[4] = {bv.x, bv.y, bv.z, bv.w};
            #pragma unroll
            for (int i = 0; i < 4; ++i)
                #pragma unroll
                for (int j = 0; j < 4; ++j)
                    acc[i][j] += ar[i] * br[j];
        }
        __syncthreads();
    }

    const int n = n0 + 4*tx;
    float4 bb = *(const float4*)&bias[n];
    #pragma unroll
    for (int i = 0; i < 4; ++i) {
        const int m = m0 + 4*ty + i;
        float4 r;
        r.x = acc[i][0] + bb.x;  r.y = acc[i][1] + bb.y;
        r.z = acc[i][2] + bb.z;  r.w = acc[i][3] + bb.w;
        if (split) {
            const int b = m >> 11;          // m / SEQ
            const int s = m & (SEQ - 1);
            const int h = n >> 6;           // n / DK
            const int d = n & (DK - 1);     // = 4*tx
            *(float4*)&out[(((size_t)(b*NHEAD + h))*SEQ + s)*DK + d] = r;
        } else {
            *(float4*)&out[(size_t)m * D_MODEL + n] = r;
        }
    }
}

// ============================================================
// Flash attention: per (b,h), Br=Bc=64, online softmax, fp32.
// grid = (SEQ/64, B*H), 256 threads (16x16), 4x4 micro-tiles.
// Qs/Ks staged transposed [d][row] (Q pre-scaled by 1/8); Vs natural [c][d];
// P staged natural [row][c]. Dynamic smem: 4 * 64 * 68 * 4 B = 69632 B.
// ============================================================
#define SD 68
#define FLASH_SMEM (4*64*SD*4)

__global__ __launch_bounds__(256) void flash_attn(
    const float* __restrict__ Q, const float* __restrict__ K,
    const float* __restrict__ V, float* __restrict__ C)
{
    extern __shared__ float sm[];
    float* Qs = sm;              // [d][row]
    float* Ks = sm + 64*SD;      // [d][col]
    float* Vs = sm + 2*64*SD;    // [c][d]
    float* Ps = sm + 3*64*SD;    // [row][c]

    const int tid = threadIdx.x;
    const int tx = tid & 15;
    const int ty = tid >> 4;
    const int q0 = blockIdx.x * 64;
    const int bh = blockIdx.y;

    const float* Qb = Q + ((size_t)bh*SEQ + q0)*DK;
    const float* Kb = K + (size_t)bh*SEQ*DK;
    const float* Vb = V + (size_t)bh*SEQ*DK;

    const int ldr = tid >> 4;         // 0..15
    const int ldc = (tid & 15) * 4;   // 0..60

    // load Q tile transposed, scaled by 1/sqrt(dk)=0.125
    #pragma unroll
    for (int rr = 0; rr < 64; rr += 16) {
        const int r = rr + ldr;
        float4 v = *(const float4*)(Qb + (size_t)r*DK + ldc);
        Qs[(ldc+0)*SD + r] = v.x * 0.125f;
        Qs[(ldc+1)*SD + r] = v.y * 0.125f;
        Qs[(ldc+2)*SD + r] = v.z * 0.125f;
        Qs[(ldc+3)*SD + r] = v.w * 0.125f;
    }

    float m_i[4], l_i[4], acc[4][4];
    #pragma unroll
    for (int i = 0; i < 4; ++i) {
        m_i[i] = -1e30f; l_i[i] = 0.f;
        #pragma unroll
        for (int j = 0; j < 4; ++j) acc[i][j] = 0.f;
    }

    for (int kv0 = 0; kv0 < SEQ; kv0 += 64) {
        // load K transposed + V natural
        #pragma unroll
        for (int rr = 0; rr < 64; rr += 16) {
            const int r = rr + ldr;
            float4 kv = *(const float4*)(Kb + (size_t)(kv0 + r)*DK + ldc);
            Ks[(ldc+0)*SD + r] = kv.x;  Ks[(ldc+1)*SD + r] = kv.y;
            Ks[(ldc+2)*SD + r] = kv.z;  Ks[(ldc+3)*SD + r] = kv.w;
            float4 vv = *(const float4*)(Vb + (size_t)(kv0 + r)*DK + ldc);
            *(float4*)&Vs[r*SD + ldc] = vv;
        }
        __syncthreads();

        // S = Q K^T (scale folded into Q)
        float s[4][4] = {};
        #pragma unroll 8
        for (int d = 0; d < 64; ++d) {
            float4 qv = *(const float4*)&Qs[d*SD + 4*ty];
            float4 kv = *(const float4*)&Ks[d*SD + 4*tx];
            float qr[4] = {qv.x, qv.y, qv.z, qv.w};
            float kr[4] = {kv.x, kv.y, kv.z, kv.w};
            #pragma unroll
            for (int i = 0; i < 4; ++i)
                #pragma unroll
                for (int j = 0; j < 4; ++j)
                    s[i][j] += qr[i] * kr[j];
        }

        // online softmax update
        #pragma unroll
        for (int i = 0; i < 4; ++i) {
            float rm = fmaxf(fmaxf(s[i][0], s[i][1]), fmaxf(s[i][2], s[i][3]));
            rm = fmaxf(rm, __shfl_xor_sync(0xffffffffu, rm, 8));
            rm = fmaxf(rm, __shfl_xor_sync(0xffffffffu, rm, 4));
            rm = fmaxf(rm, __shfl_xor_sync(0xffffffffu, rm, 2));
            rm = fmaxf(rm, __shfl_xor_sync(0xffffffffu, rm, 1));
            const float mnew = fmaxf(m_i[i], rm);
            const float corr = __expf(m_i[i] - mnew);
            float4 p;
            p.x = __expf(s[i][0] - mnew);
            p.y = __expf(s[i][1] - mnew);
            p.z = __expf(s[i][2] - mnew);
            p.w = __expf(s[i][3] - mnew);
            *(float4*)&Ps[(4*ty + i)*SD + 4*tx] = p;
            float rs = p.x + p.y + p.z + p.w;
            rs += __shfl_xor_sync(0xffffffffu, rs, 8);
            rs += __shfl_xor_sync(0xffffffffu, rs, 4);
            rs += __shfl_xor_sync(0xffffffffu, rs, 2);
            rs += __shfl_xor_sync(0xffffffffu, rs, 1);
            l_i[i] = l_i[i] * corr + rs;
            m_i[i] = mnew;
            #pragma unroll
            for (int j = 0; j < 4; ++j) acc[i][j] *= corr;
        }
        __syncthreads();

        // acc += P @ V
        #pragma unroll 8
        for (int c = 0; c < 64; ++c) {
            float4 vv = *(const float4*)&Vs[c*SD + 4*tx];
            #pragma unroll
            for (int i = 0; i < 4; ++i) {
                const float p = Ps[(4*ty + i)*SD + c];
                acc[i][0] += p * vv.x;
                acc[i][1] += p * vv.y;
                acc[i][2] += p * vv.z;
                acc[i][3] += p * vv.w;
            }
        }
        __syncthreads();
    }

    // epilogue: normalize and write combined layout [b][s][h*64+d]
    const int b = bh >> 4;
    const int h = bh & 15;
    #pragma unroll
    for (int i = 0; i < 4; ++i) {
        const int srow = q0 + 4*ty + i;
        const float inv = 1.f / l_i[i];
        float4 o;
        o.x = acc[i][0] * inv;  o.y = acc[i][1] * inv;
        o.z = acc[i][2] * inv;  o.w = acc[i][3] * inv;
        *(float4*)&C[((size_t)(b*SEQ + srow))*D_MODEL + h*DK + 4*tx] = o;
    }
}

// ============================================================
// Launch
// ============================================================
extern "C" void kernel_launch(void* const* d_in, const int* in_sizes, int n_in,
                              void* d_out, int out_size)
{
    const float* query = (const float*)d_in[0];
    const float* key   = (const float*)d_in[1];
    const float* value = (const float*)d_in[2];
    const float* W_q   = (const float*)d_in[3];
    const float* b_q   = (const float*)d_in[4];
    const float* W_k   = (const float*)d_in[5];
    const float* b_k   = (const float*)d_in[6];
    const float* W_v   = (const float*)d_in[7];
    const float* b_v   = (const float*)d_in[8];
    const float* W_o   = (const float*)d_in[9];
    const float* b_o   = (const float*)d_in[10];
    float* out = (float*)d_out;

    float *Qp, *Kp, *Vp, *Cp;
    cudaGetSymbolAddress((void**)&Qp, g_Q);
    cudaGetSymbolAddress((void**)&Kp, g_K);
    cudaGetSymbolAddress((void**)&Vp, g_V);
    cudaGetSymbolAddress((void**)&Cp, g_C);

    static int smem_set = 0;
    if (!smem_set) {
        cudaFuncSetAttribute(flash_attn,
                             cudaFuncAttributeMaxDynamicSharedMemorySize,
                             FLASH_SMEM);
        smem_set = 1;
    }

    dim3 gg(MROWS/BM, D_MODEL/BN);   // (64, 16)
    dim3 bb(256);

    gemm_xWT<<<gg, bb>>>(query, W_q, b_q, Qp, 1);
    gemm_xWT<<<gg, bb>>>(key,   W_k, b_k, Kp, 1);
    gemm_xWT<<<gg, bb>>>(value, W_v, b_v, Vp, 1);

    dim3 fg(SEQ/64, BATCH*NHEAD);    // (32, 32)
    flash_attn<<<fg, bb, FLASH_SMEM>>>(Qp, Kp, Vp, Cp);

    gemm_xWT<<<gg, bb>>>(Cp, W_o, b_o, out, 0);
}

// round 4
// speedup vs baseline: 2.2139x; 2.2139x over previous
#include <cuda_runtime.h>
#include <math.h>
#include <stdint.h>

#define D_MODEL 1024
#define NHEAD   16
#define DK      64
#define BATCH   2
#define SEQ     2048
#define MROWS   (BATCH*SEQ)   // 4096

// ---- scratch (device globals; no allocation allowed) ----
__device__ float g_Q[BATCH*NHEAD*SEQ*DK];   // [b][h][s][d]
__device__ float g_K[BATCH*NHEAD*SEQ*DK];
__device__ float g_V[BATCH*NHEAD*SEQ*DK];
__device__ float g_C[MROWS*D_MODEL];        // combined [b][s][h*64+d]

// ============================================================
// helpers
// ============================================================
__device__ __forceinline__ uint32_t cvt_tf32(float f) {
    uint32_t r;
    asm("cvt.rna.tf32.f32 %0, %1;" : "=r"(r) : "f"(f));
    return r;
}

// D += A*B, m16n8k8 tf32 (HMMA legacy path, arch-neutral PTX)
__device__ __forceinline__ void mma_tf32(float* d, const uint32_t* a,
                                         uint32_t b0, uint32_t b1) {
    asm volatile("mma.sync.aligned.m16n8k8.row.col.f32.tf32.tf32.f32 "
                 "{%0,%1,%2,%3}, {%4,%5,%6,%7}, {%8,%9}, {%0,%1,%2,%3};"
                 : "+f"(d[0]), "+f"(d[1]), "+f"(d[2]), "+f"(d[3])
                 : "r"(a[0]), "r"(a[1]), "r"(a[2]), "r"(a[3]),
                   "r"(b0), "r"(b1));
}

// ============================================================
// GEMM: out = A @ W^T + bias  (A [4096,1024], W [1024,1024] row-major)
// CTA 128x128, BK=32, 8 warps (2x4), warp tile 64x32, tf32 mma.sync.
// Double-buffered smem, register prefetch.
// ============================================================
#define GPAD 36
#define GSTG (128*GPAD)            // uint32 per operand stage
#define GEMM_SMEM (4*GSTG*4)       // 73728 B

__global__ __launch_bounds__(256) void gemm_mma(
    const float* __restrict__ A, const float* __restrict__ W,
    const float* __restrict__ bias, float* __restrict__ out, int split)
{
    extern __shared__ uint32_t su[];
    uint32_t* Asm[2] = { su,          su + GSTG   };
    uint32_t* Bsm[2] = { su + 2*GSTG, su + 3*GSTG };

    const int tid = threadIdx.x;
    const int w   = tid >> 5;
    const int lane = tid & 31;
    const int g   = lane >> 2;
    const int tig = lane & 3;
    const int wm  = w >> 2;          // 0..1
    const int wn  = w & 3;           // 0..3
    const int m0  = blockIdx.x * 128;
    const int n0  = blockIdx.y * 128;

    const int lr  = tid >> 1;              // 0..127
    const int lc0 = (tid & 1) * 16;        // 0 or 16
    const float* Ag = A + (size_t)(m0 + lr) * D_MODEL + lc0;
    const float* Wg = W + (size_t)(n0 + lr) * D_MODEL + lc0;

    float4 pa[4], pw[4];
    #pragma unroll
    for (int i = 0; i < 4; ++i) {
        pa[i] = *(const float4*)(Ag + i*4);
        pw[i] = *(const float4*)(Wg + i*4);
    }

    float acc[4][4][4];
    #pragma unroll
    for (int mt = 0; mt < 4; ++mt)
        #pragma unroll
        for (int nt = 0; nt < 4; ++nt)
            #pragma unroll
            for (int q = 0; q < 4; ++q) acc[mt][nt][q] = 0.f;

    for (int c = 0; c < 32; ++c) {
        const int buf = c & 1;
        // store prefetched chunk (cvt to tf32)
        #pragma unroll
        for (int i = 0; i < 4; ++i) {
            uint32_t* pA = &Asm[buf][lr*GPAD + lc0 + i*4];
            pA[0] = cvt_tf32(pa[i].x); pA[1] = cvt_tf32(pa[i].y);
            pA[2] = cvt_tf32(pa[i].z); pA[3] = cvt_tf32(pa[i].w);
            uint32_t* pB = &Bsm[buf][lr*GPAD + lc0 + i*4];
            pB[0] = cvt_tf32(pw[i].x); pB[1] = cvt_tf32(pw[i].y);
            pB[2] = cvt_tf32(pw[i].z); pB[3] = cvt_tf32(pw[i].w);
        }
        __syncthreads();

        if (c < 31) {
            const int k0 = (c+1) * 32;
            #pragma unroll
            for (int i = 0; i < 4; ++i) {
                pa[i] = *(const float4*)(Ag + k0 + i*4);
                pw[i] = *(const float4*)(Wg + k0 + i*4);
            }
        }

        const uint32_t* As = Asm[buf];
        const uint32_t* Bs = Bsm[buf];
        #pragma unroll
        for (int ks = 0; ks < 4; ++ks) {
            uint32_t af[4][4];
            #pragma unroll
            for (int mt = 0; mt < 4; ++mt) {
                const int ar = wm*64 + mt*16 + g;
                af[mt][0] = As[ar*GPAD     + ks*8 + tig];
                af[mt][1] = As[(ar+8)*GPAD + ks*8 + tig];
                af[mt][2] = As[ar*GPAD     + ks*8 + tig + 4];
                af[mt][3] = As[(ar+8)*GPAD + ks*8 + tig + 4];
            }
            #pragma unroll
            for (int nt = 0; nt < 4; ++nt) {
                const int bc = wn*32 + nt*8 + g;
                const uint32_t b0 = Bs[bc*GPAD + ks*8 + tig];
                const uint32_t b1 = Bs[bc*GPAD + ks*8 + tig + 4];
                #pragma unroll
                for (int mt = 0; mt < 4; ++mt)
                    mma_tf32(acc[mt][nt], af[mt], b0, b1);
            }
        }
    }

    // epilogue: rows g,g+8 per m-tile; col pairs 2tig,2tig+1 per n-tile
    #pragma unroll
    for (int mt = 0; mt < 4; ++mt) {
        #pragma unroll
        for (int nt = 0; nt < 4; ++nt) {
            const int n  = n0 + wn*32 + nt*8 + 2*tig;
            const float2 bb = *(const float2*)&bias[n];
            const int r0 = m0 + wm*64 + mt*16 + g;
            float2 v0, v1;
            v0.x = acc[mt][nt][0] + bb.x;  v0.y = acc[mt][nt][1] + bb.y;
            v1.x = acc[mt][nt][2] + bb.x;  v1.y = acc[mt][nt][3] + bb.y;
            if (split) {
                const int h = n >> 6, d = n & (DK-1);
                const int b0_ = r0 >> 11, s0_ = r0 & (SEQ-1);
                *(float2*)&out[(((size_t)(b0_*NHEAD + h))*SEQ + s0_)*DK + d] = v0;
                const int r1 = r0 + 8;
                const int b1_ = r1 >> 11, s1_ = r1 & (SEQ-1);
                *(float2*)&out[(((size_t)(b1_*NHEAD + h))*SEQ + s1_)*DK + d] = v1;
            } else {
                *(float2*)&out[(size_t)r0 * D_MODEL + n] = v0;
                *(float2*)&out[(size_t)(r0+8) * D_MODEL + n] = v1;
            }
        }
    }
}

// ============================================================
// Flash attention with tf32 mma.sync.
// Per (b,h): Br=Bc=64. 8 warps: wr=w>>1 row group (16 rows), wc=w&1 col half.
// S via mma (warp tile 16x32), softmax in regs + smem cross-half reduce,
// P round-trips smem as tf32, PV via mma (warp tile 16x32 over dk, k=64).
// ============================================================
#define FSD 68
#define FLASH_SMEM ((4*64*FSD + 256) * 4)   // 70656 B

__global__ __launch_bounds__(256) void flash_mma(
    const float* __restrict__ Q, const float* __restrict__ K,
    const float* __restrict__ V, float* __restrict__ C)
{
    extern __shared__ uint32_t su[];
    uint32_t* Qs = su;               // [row][d]
    uint32_t* Ks = su + 64*FSD;      // [kcol][d]
    uint32_t* Vs = su + 2*64*FSD;    // [c][dk]
    uint32_t* Ps = su + 3*64*FSD;    // [row][c]
    float* red   = (float*)(su + 4*64*FSD);  // [4][64]: max h0,h1, sum h0,h1

    const int tid = threadIdx.x;
    const int w   = tid >> 5;
    const int lane = tid & 31;
    const int g   = lane >> 2;
    const int tig = lane & 3;
    const int wr  = w >> 1;          // 0..3
    const int wc  = w & 1;           // 0..1
    const int q0  = blockIdx.x * 64;
    const int bh  = blockIdx.y;

    const float* Qb = Q + ((size_t)bh*SEQ + q0)*DK;
    const float* Kb = K + (size_t)bh*SEQ*DK;
    const float* Vb = V + (size_t)bh*SEQ*DK;

    // stage Q (scaled by 1/8, tf32)
    #pragma unroll
    for (int i = 0; i < 4; ++i) {
        const int fidx = tid + 256*i;        // 1024 float4 slots
        const int r = fidx >> 4, col = (fidx & 15) * 4;
        float4 v = *(const float4*)(Qb + (size_t)r*DK + col);
        uint32_t* p = &Qs[r*FSD + col];
        p[0] = cvt_tf32(v.x * 0.125f); p[1] = cvt_tf32(v.y * 0.125f);
        p[2] = cvt_tf32(v.z * 0.125f); p[3] = cvt_tf32(v.w * 0.125f);
    }

    const int row0 = wr*16 + g;      // thread's first row (second = +8)
    float m0r = -1e30f, m1r = -1e30f, l0r = 0.f, l1r = 0.f;
    float acc[4][4];
    #pragma unroll
    for (int nt = 0; nt < 4; ++nt)
        #pragma unroll
        for (int q = 0; q < 4; ++q) acc[nt][q] = 0.f;

    for (int kv0 = 0; kv0 < SEQ; kv0 += 64) {
        __syncthreads();   // prev iter PV / red reads done
        // stage K, V (tf32)
        #pragma unroll
        for (int i = 0; i < 4; ++i) {
            const int fidx = tid + 256*i;
            const int r = fidx >> 4, col = (fidx & 15) * 4;
            float4 kv = *(const float4*)(Kb + (size_t)(kv0 + r)*DK + col);
            uint32_t* pk = &Ks[r*FSD + col];
            pk[0] = cvt_tf32(kv.x); pk[1] = cvt_tf32(kv.y);
            pk[2] = cvt_tf32(kv.z); pk[3] = cvt_tf32(kv.w);
            float4 vv = *(const float4*)(Vb + (size_t)(kv0 + r)*DK + col);
            uint32_t* pv = &Vs[r*FSD + col];
            pv[0] = cvt_tf32(vv.x); pv[1] = cvt_tf32(vv.y);
            pv[2] = cvt_tf32(vv.z); pv[3] = cvt_tf32(vv.w);
        }
        __syncthreads();

        // ---- S = Q K^T (warp tile 16x32) ----
        float s[4][4];
        #pragma unroll
        for (int nt = 0; nt < 4; ++nt)
            #pragma unroll
            for (int q = 0; q < 4; ++q) s[nt][q] = 0.f;
        #pragma unroll
        for (int ks = 0; ks < 8; ++ks) {
            uint32_t a[4];
            a[0] = Qs[row0*FSD     + ks*8 + tig];
            a[1] = Qs[(row0+8)*FSD + ks*8 + tig];
            a[2] = Qs[row0*FSD     + ks*8 + tig + 4];
            a[3] = Qs[(row0+8)*FSD + ks*8 + tig + 4];
            #pragma unroll
            for (int nt = 0; nt < 4; ++nt) {
                const int bc = wc*32 + nt*8 + g;
                mma_tf32(s[nt], a,
                         Ks[bc*FSD + ks*8 + tig],
                         Ks[bc*FSD + ks*8 + tig + 4]);
            }
        }

        // ---- softmax ----
        float rm0 = -1e30f, rm1 = -1e30f;
        #pragma unroll
        for (int nt = 0; nt < 4; ++nt) {
            rm0 = fmaxf(rm0, fmaxf(s[nt][0], s[nt][1]));
            rm1 = fmaxf(rm1, fmaxf(s[nt][2], s[nt][3]));
        }
        rm0 = fmaxf(rm0, __shfl_xor_sync(0xffffffffu, rm0, 1));
        rm0 = fmaxf(rm0, __shfl_xor_sync(0xffffffffu, rm0, 2));
        rm1 = fmaxf(rm1, __shfl_xor_sync(0xffffffffu, rm1, 1));
        rm1 = fmaxf(rm1, __shfl_xor_sync(0xffffffffu, rm1, 2));
        if (tig == 0) {
            red[wc*64 + row0]     = rm0;
            red[wc*64 + row0 + 8] = rm1;
        }
        __syncthreads();
        const float om0 = fmaxf(red[row0],     red[64 + row0]);
        const float om1 = fmaxf(red[row0 + 8], red[64 + row0 + 8]);
        const float mn0 = fmaxf(m0r, om0);
        const float mn1 = fmaxf(m1r, om1);
        const float cr0 = __expf(m0r - mn0);
        const float cr1 = __expf(m1r - mn1);

        float sum0 = 0.f, sum1 = 0.f;
        #pragma unroll
        for (int nt = 0; nt < 4; ++nt) {
            float p0 = __expf(s[nt][0] - mn0);
            float p1 = __expf(s[nt][1] - mn0);
            float p2 = __expf(s[nt][2] - mn1);
            float p3 = __expf(s[nt][3] - mn1);
            sum0 += p0 + p1;  sum1 += p2 + p3;
            const int pc = wc*32 + nt*8 + 2*tig;
            uint32_t* pp0 = &Ps[row0*FSD + pc];
            pp0[0] = cvt_tf32(p0); pp0[1] = cvt_tf32(p1);
            uint32_t* pp1 = &Ps[(row0+8)*FSD + pc];
            pp1[0] = cvt_tf32(p2); pp1[1] = cvt_tf32(p3);
        }
        sum0 += __shfl_xor_sync(0xffffffffu, sum0, 1);
        sum0 += __shfl_xor_sync(0xffffffffu, sum0, 2);
        sum1 += __shfl_xor_sync(0xffffffffu, sum1, 1);
        sum1 += __shfl_xor_sync(0xffffffffu, sum1, 2);
        if (tig == 0) {
            red[128 + wc*64 + row0]     = sum0;
            red[128 + wc*64 + row0 + 8] = sum1;
        }
        __syncthreads();   // sums + P visible
        l0r = l0r * cr0 + red[128 + row0]     + red[192 + row0];
        l1r = l1r * cr1 + red[128 + row0 + 8] + red[192 + row0 + 8];
        m0r = mn0;  m1r = mn1;

        #pragma unroll
        for (int nt = 0; nt < 4; ++nt) {
            acc[nt][0] *= cr0;  acc[nt][1] *= cr0;
            acc[nt][2] *= cr1;  acc[nt][3] *= cr1;
        }

        // ---- O += P V (warp tile 16x32 over dk, k = 64) ----
        #pragma unroll
        for (int ks = 0; ks < 8; ++ks) {
            uint32_t a[4];
            a[0] = Ps[row0*FSD     + ks*8 + tig];
            a[1] = Ps[(row0+8)*FSD + ks*8 + tig];
            a[2] = Ps[row0*FSD     + ks*8 + tig + 4];
            a[3] = Ps[(row0+8)*FSD + ks*8 + tig + 4];
            #pragma unroll
            for (int nt = 0; nt < 4; ++nt) {
                const int vc = wc*32 + nt*8 + g;
                mma_tf32(acc[nt], a,
                         Vs[(ks*8 + tig)*FSD + vc],
                         Vs[(ks*8 + tig + 4)*FSD + vc]);
            }
        }
    }

    // epilogue
    const int b = bh >> 4;
    const int h = bh & 15;
    const float inv0 = 1.f / l0r;
    const float inv1 = 1.f / l1r;
    #pragma unroll
    for (int nt = 0; nt < 4; ++nt) {
        const int col = h*DK + wc*32 + nt*8 + 2*tig;
        float2 v0, v1;
        v0.x = acc[nt][0] * inv0;  v0.y = acc[nt][1] * inv0;
        v1.x = acc[nt][2] * inv1;  v1.y = acc[nt][3] * inv1;
        const int r0g = q0 + row0;
        *(float2*)&C[((size_t)(b*SEQ + r0g))*D_MODEL + col] = v0;
        *(float2*)&C[((size_t)(b*SEQ + r0g + 8))*D_MODEL + col] = v1;
    }
}

// ============================================================
// Launch
// ============================================================
extern "C" void kernel_launch(void* const* d_in, const int* in_sizes, int n_in,
                              void* d_out, int out_size)
{
    const float* query = (const float*)d_in[0];
    const float* key   = (const float*)d_in[1];
    const float* value = (const float*)d_in[2];
    const float* W_q   = (const float*)d_in[3];
    const float* b_q   = (const float*)d_in[4];
    const float* W_k   = (const float*)d_in[5];
    const float* b_k   = (const float*)d_in[6];
    const float* W_v   = (const float*)d_in[7];
    const float* b_v   = (const float*)d_in[8];
    const float* W_o   = (const float*)d_in[9];
    const float* b_o   = (const float*)d_in[10];
    float* out = (float*)d_out;

    float *Qp, *Kp, *Vp, *Cp;
    cudaGetSymbolAddress((void**)&Qp, g_Q);
    cudaGetSymbolAddress((void**)&Kp, g_K);
    cudaGetSymbolAddress((void**)&Vp, g_V);
    cudaGetSymbolAddress((void**)&Cp, g_C);

    static int attr_set = 0;
    if (!attr_set) {
        cudaFuncSetAttribute(gemm_mma,
                             cudaFuncAttributeMaxDynamicSharedMemorySize,
                             GEMM_SMEM);
        cudaFuncSetAttribute(flash_mma,
                             cudaFuncAttributeMaxDynamicSharedMemorySize,
                             FLASH_SMEM);
        attr_set = 1;
    }

    dim3 gg(MROWS/128, D_MODEL/128);   // (32, 8)
    dim3 bb(256);

    gemm_mma<<<gg, bb, GEMM_SMEM>>>(query, W_q, b_q, Qp, 1);
    gemm_mma<<<gg, bb, GEMM_SMEM>>>(key,   W_k, b_k, Kp, 1);
    gemm_mma<<<gg, bb, GEMM_SMEM>>>(value, W_v, b_v, Vp, 1);

    dim3 fg(SEQ/64, BATCH*NHEAD);      // (32, 32)
    flash_mma<<<fg, bb, FLASH_SMEM>>>(Qp, Kp, Vp, Cp);

    gemm_mma<<<gg, bb, GEMM_SMEM>>>(Cp, W_o, b_o, out, 0);
}

// round 5
// speedup vs baseline: 2.6480x; 1.1961x over previous
#include <cuda_runtime.h>
#include <math.h>
#include <stdint.h>

#define D_MODEL 1024
#define NHEAD   16
#define DK      64
#define BATCH   2
#define SEQ     2048
#define MROWS   (BATCH*SEQ)   // 4096

// ---- scratch (device globals; no allocation allowed) ----
__device__ float g_Q[BATCH*NHEAD*SEQ*DK];   // [b][h][s][d]
__device__ float g_K[BATCH*NHEAD*SEQ*DK];
__device__ float g_V[BATCH*NHEAD*SEQ*DK];
__device__ float g_C[MROWS*D_MODEL];        // combined [b][s][h*64+d]

// ============================================================
// helpers
// ============================================================
__device__ __forceinline__ uint32_t cvt_tf32(float f) {
    uint32_t r;
    asm("cvt.rna.tf32.f32 %0, %1;" : "=r"(r) : "f"(f));
    return r;
}
__device__ __forceinline__ float ex2(float x) {
    float r;
    asm("ex2.approx.f32 %0, %1;" : "=f"(r) : "f"(x));
    return r;
}

// D += A*B, m16n8k8 tf32 (HMMA legacy path, arch-neutral PTX)
__device__ __forceinline__ void mma_tf32(float* d, const uint32_t* a,
                                         uint32_t b0, uint32_t b1) {
    asm volatile("mma.sync.aligned.m16n8k8.row.col.f32.tf32.tf32.f32 "
                 "{%0,%1,%2,%3}, {%4,%5,%6,%7}, {%8,%9}, {%0,%1,%2,%3};"
                 : "+f"(d[0]), "+f"(d[1]), "+f"(d[2]), "+f"(d[3])
                 : "r"(a[0]), "r"(a[1]), "r"(a[2]), "r"(a[3]),
                   "r"(b0), "r"(b1));
}

// ============================================================
// GEMM: out = A @ W^T + bias  (A [4096,1024], W [1024,1024] row-major)
// CTA 128x128, BK=32, 8 warps (2x4), warp tile 64x32, tf32 mma.sync.
// Double-buffered smem, register prefetch, v4 staging stores.
// blockIdx.z selects (A, W, bias, out) triple -> QKV fused in one launch.
// ============================================================
#define GPAD 36
#define GSTG (128*GPAD)            // uint32 per operand stage
#define GEMM_SMEM (4*GSTG*4)       // 73728 B

__global__ __launch_bounds__(256) void gemm_mma(
    const float* __restrict__ A0, const float* __restrict__ A1,
    const float* __restrict__ A2,
    const float* __restrict__ W0, const float* __restrict__ W1,
    const float* __restrict__ W2,
    const float* __restrict__ bias0, const float* __restrict__ bias1,
    const float* __restrict__ bias2,
    float* __restrict__ O0, float* __restrict__ O1, float* __restrict__ O2,
    int split)
{
    extern __shared__ uint32_t su[];
    uint32_t* Asm[2] = { su,          su + GSTG   };
    uint32_t* Bsm[2] = { su + 2*GSTG, su + 3*GSTG };

    const int z = blockIdx.z;
    const float* A    = (z == 0) ? A0 : (z == 1) ? A1 : A2;
    const float* W    = (z == 0) ? W0 : (z == 1) ? W1 : W2;
    const float* bias = (z == 0) ? bias0 : (z == 1) ? bias1 : bias2;
    float* out        = (z == 0) ? O0 : (z == 1) ? O1 : O2;

    const int tid = threadIdx.x;
    const int w   = tid >> 5;
    const int lane = tid & 31;
    const int g   = lane >> 2;
    const int tig = lane & 3;
    const int wm  = w >> 2;          // 0..1
    const int wn  = w & 3;           // 0..3
    const int m0  = blockIdx.x * 128;
    const int n0  = blockIdx.y * 128;

    const int lr  = tid >> 1;              // 0..127
    const int lc0 = (tid & 1) * 16;        // 0 or 16
    const float* Ag = A + (size_t)(m0 + lr) * D_MODEL + lc0;
    const float* Wg = W + (size_t)(n0 + lr) * D_MODEL + lc0;

    float4 pa[4], pw[4];
    #pragma unroll
    for (int i = 0; i < 4; ++i) {
        pa[i] = *(const float4*)(Ag + i*4);
        pw[i] = *(const float4*)(Wg + i*4);
    }

    float acc[4][4][4];
    #pragma unroll
    for (int mt = 0; mt < 4; ++mt)
        #pragma unroll
        for (int nt = 0; nt < 4; ++nt)
            #pragma unroll
            for (int q = 0; q < 4; ++q) acc[mt][nt][q] = 0.f;

    for (int c = 0; c < 32; ++c) {
        const int buf = c & 1;
        #pragma unroll
        for (int i = 0; i < 4; ++i) {
            uint4 va = make_uint4(cvt_tf32(pa[i].x), cvt_tf32(pa[i].y),
                                  cvt_tf32(pa[i].z), cvt_tf32(pa[i].w));
            *(uint4*)&Asm[buf][lr*GPAD + lc0 + i*4] = va;
            uint4 vb = make_uint4(cvt_tf32(pw[i].x), cvt_tf32(pw[i].y),
                                  cvt_tf32(pw[i].z), cvt_tf32(pw[i].w));
            *(uint4*)&Bsm[buf][lr*GPAD + lc0 + i*4] = vb;
        }
        __syncthreads();

        if (c < 31) {
            const int k0 = (c+1) * 32;
            #pragma unroll
            for (int i = 0; i < 4; ++i) {
                pa[i] = *(const float4*)(Ag + k0 + i*4);
                pw[i] = *(const float4*)(Wg + k0 + i*4);
            }
        }

        const uint32_t* As = Asm[buf];
        const uint32_t* Bs = Bsm[buf];
        #pragma unroll
        for (int ks = 0; ks < 4; ++ks) {
            uint32_t af[4][4];
            #pragma unroll
            for (int mt = 0; mt < 4; ++mt) {
                const int ar = wm*64 + mt*16 + g;
                af[mt][0] = As[ar*GPAD     + ks*8 + tig];
                af[mt][1] = As[(ar+8)*GPAD + ks*8 + tig];
                af[mt][2] = As[ar*GPAD     + ks*8 + tig + 4];
                af[mt][3] = As[(ar+8)*GPAD + ks*8 + tig + 4];
            }
            #pragma unroll
            for (int nt = 0; nt < 4; ++nt) {
                const int bc = wn*32 + nt*8 + g;
                const uint32_t b0 = Bs[bc*GPAD + ks*8 + tig];
                const uint32_t b1 = Bs[bc*GPAD + ks*8 + tig + 4];
                #pragma unroll
                for (int mt = 0; mt < 4; ++mt)
                    mma_tf32(acc[mt][nt], af[mt], b0, b1);
            }
        }
    }

    #pragma unroll
    for (int mt = 0; mt < 4; ++mt) {
        #pragma unroll
        for (int nt = 0; nt < 4; ++nt) {
            const int n  = n0 + wn*32 + nt*8 + 2*tig;
            const float2 bb = *(const float2*)&bias[n];
            const int r0 = m0 + wm*64 + mt*16 + g;
            float2 v0, v1;
            v0.x = acc[mt][nt][0] + bb.x;  v0.y = acc[mt][nt][1] + bb.y;
            v1.x = acc[mt][nt][2] + bb.x;  v1.y = acc[mt][nt][3] + bb.y;
            if (split) {
                const int h = n >> 6, d = n & (DK-1);
                const int b0_ = r0 >> 11, s0_ = r0 & (SEQ-1);
                *(float2*)&out[(((size_t)(b0_*NHEAD + h))*SEQ + s0_)*DK + d] = v0;
                const int r1 = r0 + 8;
                const int b1_ = r1 >> 11, s1_ = r1 & (SEQ-1);
                *(float2*)&out[(((size_t)(b1_*NHEAD + h))*SEQ + s1_)*DK + d] = v1;
            } else {
                *(float2*)&out[(size_t)r0 * D_MODEL + n] = v0;
                *(float2*)&out[(size_t)(r0+8) * D_MODEL + n] = v1;
            }
        }
    }
}

// ============================================================
// Flash attention v2: Br=128, Bc=64, tf32 mma.sync.
// 8 warps, warp w owns rows w*16..w*16+15 x ALL 64 kv cols ->
// warp-local softmax (shfl only). P stays in registers: quad-shuffle
// permute from accumulator layout to A-fragment layout, feed PV mma
// as raw f32 (HW truncation to tf32).
// smem: Qs [128][68] tf32 (scale*log2e folded), Ks [64][68], Vs [64][72].
// ============================================================
#define FQ 68
#define FV 72
#define FLASH_SMEM ((128*FQ + 64*FQ + 64*FV) * 4)   // 70656 B
#define QSCALE (0.125f * 1.44269504088896340736f)   // 1/sqrt(dk) * log2(e)

__global__ __launch_bounds__(256) void flash_mma(
    const float* __restrict__ Q, const float* __restrict__ K,
    const float* __restrict__ V, float* __restrict__ C)
{
    extern __shared__ uint32_t su[];
    uint32_t* Qs = su;                    // [128][FQ]
    uint32_t* Ks = su + 128*FQ;           // [64][FQ]
    uint32_t* Vs = su + 128*FQ + 64*FQ;   // [64][FV]

    const int tid = threadIdx.x;
    const int w   = tid >> 5;
    const int lane = tid & 31;
    const int g   = lane >> 2;
    const int tig = lane & 3;
    const int q0  = blockIdx.x * 128;
    const int bh  = blockIdx.y;

    const float* Qb = Q + ((size_t)bh*SEQ + q0)*DK;
    const float* Kb = K + (size_t)bh*SEQ*DK;
    const float* Vb = V + (size_t)bh*SEQ*DK;

    // stage Q once: 128 rows x 16 float4 = 2048 slots, 8 per thread
    #pragma unroll
    for (int i = 0; i < 8; ++i) {
        const int fidx = tid + 256*i;
        const int r = fidx >> 4, col = (fidx & 15) * 4;
        float4 v = *(const float4*)(Qb + (size_t)r*DK + col);
        uint4 u = make_uint4(cvt_tf32(v.x * QSCALE), cvt_tf32(v.y * QSCALE),
                             cvt_tf32(v.z * QSCALE), cvt_tf32(v.w * QSCALE));
        *(uint4*)&Qs[r*FQ + col] = u;
    }

    const int row0 = w*16 + g;
    float m0r = -1e30f, m1r = -1e30f, l0r = 0.f, l1r = 0.f;
    float acc[8][4];
    #pragma unroll
    for (int nt = 0; nt < 8; ++nt)
        #pragma unroll
        for (int q = 0; q < 4; ++q) acc[nt][q] = 0.f;

    for (int kv0 = 0; kv0 < SEQ; kv0 += 64) {
        __syncthreads();   // prior iter reads of Ks/Vs complete
        // stage K, V: 64 rows x 16 float4 each; 4 per thread per tensor
        #pragma unroll
        for (int i = 0; i < 4; ++i) {
            const int fidx = tid + 256*i;
            const int r = fidx >> 4, col = (fidx & 15) * 4;
            float4 kv = *(const float4*)(Kb + (size_t)(kv0 + r)*DK + col);
            uint4 uk = make_uint4(cvt_tf32(kv.x), cvt_tf32(kv.y),
                                  cvt_tf32(kv.z), cvt_tf32(kv.w));
            *(uint4*)&Ks[r*FQ + col] = uk;
            float4 vv = *(const float4*)(Vb + (size_t)(kv0 + r)*DK + col);
            uint4 uv = make_uint4(cvt_tf32(vv.x), cvt_tf32(vv.y),
                                  cvt_tf32(vv.z), cvt_tf32(vv.w));
            *(uint4*)&Vs[r*FV + col] = uv;
        }
        __syncthreads();

        // ---- S = Q K^T (log2 domain), warp tile 16x64 ----
        float s[8][4];
        #pragma unroll
        for (int nt = 0; nt < 8; ++nt)
            #pragma unroll
            for (int q = 0; q < 4; ++q) s[nt][q] = 0.f;
        #pragma unroll
        for (int ks = 0; ks < 8; ++ks) {
            uint32_t a[4];
            a[0] = Qs[row0*FQ     + ks*8 + tig];
            a[1] = Qs[(row0+8)*FQ + ks*8 + tig];
            a[2] = Qs[row0*FQ     + ks*8 + tig + 4];
            a[3] = Qs[(row0+8)*FQ + ks*8 + tig + 4];
            #pragma unroll
            for (int nt = 0; nt < 8; ++nt) {
                const int bc = nt*8 + g;
                mma_tf32(s[nt], a,
                         Ks[bc*FQ + ks*8 + tig],
                         Ks[bc*FQ + ks*8 + tig + 4]);
            }
        }

        // ---- warp-local online softmax (base 2) ----
        float mx0 = -1e30f, mx1 = -1e30f;
        #pragma unroll
        for (int nt = 0; nt < 8; ++nt) {
            mx0 = fmaxf(mx0, fmaxf(s[nt][0], s[nt][1]));
            mx1 = fmaxf(mx1, fmaxf(s[nt][2], s[nt][3]));
        }
        mx0 = fmaxf(mx0, __shfl_xor_sync(0xffffffffu, mx0, 1));
        mx0 = fmaxf(mx0, __shfl_xor_sync(0xffffffffu, mx0, 2));
        mx1 = fmaxf(mx1, __shfl_xor_sync(0xffffffffu, mx1, 1));
        mx1 = fmaxf(mx1, __shfl_xor_sync(0xffffffffu, mx1, 2));
        const float mn0 = fmaxf(m0r, mx0);
        const float mn1 = fmaxf(m1r, mx1);
        const float cr0 = ex2(m0r - mn0);
        const float cr1 = ex2(m1r - mn1);

        float sum0 = 0.f, sum1 = 0.f;
        #pragma unroll
        for (int nt = 0; nt < 8; ++nt) {
            s[nt][0] = ex2(s[nt][0] - mn0);
            s[nt][1] = ex2(s[nt][1] - mn0);
            s[nt][2] = ex2(s[nt][2] - mn1);
            s[nt][3] = ex2(s[nt][3] - mn1);
            sum0 += s[nt][0] + s[nt][1];
            sum1 += s[nt][2] + s[nt][3];
        }
        sum0 += __shfl_xor_sync(0xffffffffu, sum0, 1);
        sum0 += __shfl_xor_sync(0xffffffffu, sum0, 2);
        sum1 += __shfl_xor_sync(0xffffffffu, sum1, 1);
        sum1 += __shfl_xor_sync(0xffffffffu, sum1, 2);
        l0r = l0r * cr0 + sum0;
        l1r = l1r * cr1 + sum1;
        m0r = mn0;  m1r = mn1;

        #pragma unroll
        for (int nt = 0; nt < 8; ++nt) {
            acc[nt][0] *= cr0;  acc[nt][1] *= cr0;
            acc[nt][2] *= cr1;  acc[nt][3] *= cr1;
        }

        // ---- O += P V: permute P frags via quad shuffles ----
        const int l1 = (lane & ~3) | (tig >> 1);
        const int l2 = l1 + 2;
        const bool odd = (tig & 1);
        #pragma unroll
        for (int ks = 0; ks < 8; ++ks) {
            float b0v = __shfl_sync(0xffffffffu, s[ks][0], l1);
            float b1v = __shfl_sync(0xffffffffu, s[ks][1], l1);
            float c0v = __shfl_sync(0xffffffffu, s[ks][2], l1);
            float c1v = __shfl_sync(0xffffffffu, s[ks][3], l1);
            float d0v = __shfl_sync(0xffffffffu, s[ks][0], l2);
            float d1v = __shfl_sync(0xffffffffu, s[ks][1], l2);
            float e0v = __shfl_sync(0xffffffffu, s[ks][2], l2);
            float e1v = __shfl_sync(0xffffffffu, s[ks][3], l2);
            uint32_t a[4];
            a[0] = __float_as_uint(odd ? b1v : b0v);
            a[1] = __float_as_uint(odd ? c1v : c0v);
            a[2] = __float_as_uint(odd ? d1v : d0v);
            a[3] = __float_as_uint(odd ? e1v : e0v);
            #pragma unroll
            for (int nt = 0; nt < 8; ++nt) {
                mma_tf32(acc[nt], a,
                         Vs[(ks*8 + tig)*FV     + nt*8 + g],
                         Vs[(ks*8 + tig + 4)*FV + nt*8 + g]);
            }
        }
    }

    // epilogue
    const int b = bh >> 4;
    const int h = bh & 15;
    const float inv0 = 1.f / l0r;
    const float inv1 = 1.f / l1r;
    const int r0g = q0 + row0;
    #pragma unroll
    for (int nt = 0; nt < 8; ++nt) {
        const int col = h*DK + nt*8 + 2*tig;
        float2 v0, v1;
        v0.x = acc[nt][0] * inv0;  v0.y = acc[nt][1] * inv0;
        v1.x = acc[nt][2] * inv1;  v1.y = acc[nt][3] * inv1;
        *(float2*)&g_C[((size_t)(b*SEQ + r0g))*D_MODEL + col] = v0;
        *(float2*)&g_C[((size_t)(b*SEQ + r0g + 8))*D_MODEL + col] = v1;
    }
    (void)C;
}

// ============================================================
// Launch
// ============================================================
extern "C" void kernel_launch(void* const* d_in, const int* in_sizes, int n_in,
                              void* d_out, int out_size)
{
    const float* query = (const float*)d_in[0];
    const float* key   = (const float*)d_in[1];
    const float* value = (const float*)d_in[2];
    const float* W_q   = (const float*)d_in[3];
    const float* b_q   = (const float*)d_in[4];
    const float* W_k   = (const float*)d_in[5];
    const float* b_k   = (const float*)d_in[6];
    const float* W_v   = (const float*)d_in[7];
    const float* b_v   = (const float*)d_in[8];
    const float* W_o   = (const float*)d_in[9];
    const float* b_o   = (const float*)d_in[10];
    float* out = (float*)d_out;

    float *Qp, *Kp, *Vp, *Cp;
    cudaGetSymbolAddress((void**)&Qp, g_Q);
    cudaGetSymbolAddress((void**)&Kp, g_K);
    cudaGetSymbolAddress((void**)&Vp, g_V);
    cudaGetSymbolAddress((void**)&Cp, g_C);

    static int attr_set = 0;
    if (!attr_set) {
        cudaFuncSetAttribute(gemm_mma,
                             cudaFuncAttributeMaxDynamicSharedMemorySize,
                             GEMM_SMEM);
        cudaFuncSetAttribute(flash_mma,
                             cudaFuncAttributeMaxDynamicSharedMemorySize,
                             FLASH_SMEM);
        attr_set = 1;
    }

    dim3 bb(256);

    // fused QKV projections: grid.z selects the triple
    dim3 gqkv(MROWS/128, D_MODEL/128, 3);
    gemm_mma<<<gqkv, bb, GEMM_SMEM>>>(query, key, value,
                                      W_q, W_k, W_v,
                                      b_q, b_k, b_v,
                                      Qp, Kp, Vp, 1);

    dim3 fg(SEQ/128, BATCH*NHEAD);     // (16, 32)
    flash_mma<<<fg, bb, FLASH_SMEM>>>(Qp, Kp, Vp, Cp);

    dim3 go(MROWS/128, D_MODEL/128, 1);
    gemm_mma<<<go, bb, GEMM_SMEM>>>(Cp, Cp, Cp,
                                    W_o, W_o, W_o,
                                    b_o, b_o, b_o,
                                    out, out, out, 0);
}

// round 6
// speedup vs baseline: 3.0025x; 1.1339x over previous
#include <cuda_runtime.h>
#include <math.h>
#include <stdint.h>

#define D_MODEL 1024
#define NHEAD   16
#define DK      64
#define BATCH   2
#define SEQ     2048
#define MROWS   (BATCH*SEQ)   // 4096

#define QSCALE (0.125f * 1.44269504088896340736f)   // 1/sqrt(dk) * log2(e)

// ---- scratch (device globals; no allocation allowed) ----
__device__ float g_Q[BATCH*NHEAD*SEQ*DK];   // [b][h][s][d] (tf32-rounded, scaled)
__device__ float g_K[BATCH*NHEAD*SEQ*DK];   // tf32-rounded
__device__ float g_V[BATCH*NHEAD*SEQ*DK];   // tf32-rounded
__device__ float g_C[MROWS*D_MODEL];        // combined, tf32-rounded
__device__ float g_Xr[3*MROWS*D_MODEL];     // rounded query/key/value
__device__ float g_Wr[4*D_MODEL*D_MODEL];   // rounded W_q/W_k/W_v/W_o

// ============================================================
// helpers
// ============================================================
__device__ __forceinline__ uint32_t smem_u32(const void* p) {
    uint32_t a;
    asm("{ .reg .u64 t; cvta.to.shared.u64 t, %1; cvt.u32.u64 %0, t; }"
        : "=r"(a) : "l"(p));
    return a;
}
__device__ __forceinline__ uint32_t cvt_tf32(float f) {
    uint32_t r;
    asm("cvt.rna.tf32.f32 %0, %1;" : "=r"(r) : "f"(f));
    return r;
}
__device__ __forceinline__ float ex2(float x) {
    float r;
    asm("ex2.approx.f32 %0, %1;" : "=f"(r) : "f"(x));
    return r;
}
#define CP16(dst, src) \
    asm volatile("cp.async.cg.shared.global [%0], [%1], 16;" \
                 :: "r"(dst), "l"(src) : "memory")
#define CPCOMMIT() asm volatile("cp.async.commit_group;" ::: "memory")
#define CPWAIT0()  asm volatile("cp.async.wait_group 0;" ::: "memory")

// D += A*B, m16n8k8 tf32 (operands are pre-rounded tf32 values in f32 regs)
__device__ __forceinline__ void mma_tf32(float* d, const uint32_t* a,
                                         uint32_t b0, uint32_t b1) {
    asm volatile("mma.sync.aligned.m16n8k8.row.col.f32.tf32.tf32.f32 "
                 "{%0,%1,%2,%3}, {%4,%5,%6,%7}, {%8,%9}, {%0,%1,%2,%3};"
                 : "+f"(d[0]), "+f"(d[1]), "+f"(d[2]), "+f"(d[3])
                 : "r"(a[0]), "r"(a[1]), "r"(a[2]), "r"(a[3]),
                   "r"(b0), "r"(b1));
}

// ============================================================
// pre-round pass: dst = tf32_rne(src), float4-vectorized, grid.y picks tensor
// ============================================================
__global__ __launch_bounds__(256) void round_prep(
    const float* __restrict__ s0, const float* __restrict__ s1,
    const float* __restrict__ s2, const float* __restrict__ s3,
    float* __restrict__ d0, float* __restrict__ d1,
    float* __restrict__ d2, float* __restrict__ d3, int n4)
{
    const int z = blockIdx.y;
    const float4* s = (const float4*)((z == 0) ? s0 : (z == 1) ? s1
                                    : (z == 2) ? s2 : s3);
    uint4* d = (uint4*)((z == 0) ? d0 : (z == 1) ? d1 : (z == 2) ? d2 : d3);
    for (int i = blockIdx.x * blockDim.x + threadIdx.x; i < n4;
         i += gridDim.x * blockDim.x) {
        float4 v = s[i];
        d[i] = make_uint4(cvt_tf32(v.x), cvt_tf32(v.y),
                          cvt_tf32(v.z), cvt_tf32(v.w));
    }
}

// ============================================================
// GEMM v3: out = A @ W^T + bias. Operands pre-rounded tf32-in-f32.
// CTA 128x128, BK=32, 8 warps (2x4), warp tile 64x32.
// cp.async double-buffered staging (no cvt, no prefetch regs).
// split==1: write tf32-rounded split-head (z==0 additionally scaled QSCALE).
// ============================================================
#define GPAD 36
#define GSTG (128*GPAD)            // uint32 per operand stage
#define GEMM_SMEM (4*GSTG*4)       // 73728 B

__global__ __launch_bounds__(256, 2) void gemm_mma(
    const float* __restrict__ A0, const float* __restrict__ A1,
    const float* __restrict__ A2,
    const float* __restrict__ W0, const float* __restrict__ W1,
    const float* __restrict__ W2,
    const float* __restrict__ bias0, const float* __restrict__ bias1,
    const float* __restrict__ bias2,
    float* __restrict__ O0, float* __restrict__ O1, float* __restrict__ O2,
    int split)
{
    extern __shared__ uint32_t su[];
    const uint32_t sbase = smem_u32(su);

    const int z = blockIdx.z;
    const float* A    = (z == 0) ? A0 : (z == 1) ? A1 : A2;
    const float* W    = (z == 0) ? W0 : (z == 1) ? W1 : W2;
    const float* bias = (z == 0) ? bias0 : (z == 1) ? bias1 : bias2;
    float* out        = (z == 0) ? O0 : (z == 1) ? O1 : O2;

    const int tid = threadIdx.x;
    const int w   = tid >> 5;
    const int lane = tid & 31;
    const int g   = lane >> 2;
    const int tig = lane & 3;
    const int wm  = w >> 2;          // 0..1
    const int wn  = w & 3;           // 0..3
    const int m0  = blockIdx.x * 128;
    const int n0  = blockIdx.y * 128;

    const int lr  = tid >> 1;              // 0..127
    const int lc0 = (tid & 1) * 16;        // 0 or 16
    const float* Ag = A + (size_t)(m0 + lr) * D_MODEL + lc0;
    const float* Wg = W + (size_t)(n0 + lr) * D_MODEL + lc0;
    const uint32_t dA = sbase + (uint32_t)(lr*GPAD + lc0) * 4;
    const uint32_t dB = dA + GSTG*4;

    float acc[4][4][4];
    #pragma unroll
    for (int mt = 0; mt < 4; ++mt)
        #pragma unroll
        for (int nt = 0; nt < 4; ++nt)
            #pragma unroll
            for (int q = 0; q < 4; ++q) acc[mt][nt][q] = 0.f;

    // prologue: stage chunk 0 into buffer 0
    #pragma unroll
    for (int i = 0; i < 4; ++i) {
        CP16(dA + 16*i, Ag + 4*i);
        CP16(dB + 16*i, Wg + 4*i);
    }
    CPCOMMIT();

    for (int c = 0; c < 32; ++c) {
        CPWAIT0();
        __syncthreads();
        if (c < 31) {
            const int k0 = (c+1) * 32;
            const uint32_t boff = (uint32_t)(((c+1) & 1) * 2*GSTG) * 4;
            #pragma unroll
            for (int i = 0; i < 4; ++i) {
                CP16(dA + boff + 16*i, Ag + k0 + 4*i);
                CP16(dB + boff + 16*i, Wg + k0 + 4*i);
            }
            CPCOMMIT();
        }

        const uint32_t* As = su + (c & 1) * 2*GSTG;
        const uint32_t* Bs = As + GSTG;
        #pragma unroll
        for (int ks = 0; ks < 4; ++ks) {
            uint32_t af[4][4];
            #pragma unroll
            for (int mt = 0; mt < 4; ++mt) {
                const int ar = wm*64 + mt*16 + g;
                af[mt][0] = As[ar*GPAD     + ks*8 + tig];
                af[mt][1] = As[(ar+8)*GPAD + ks*8 + tig];
                af[mt][2] = As[ar*GPAD     + ks*8 + tig + 4];
                af[mt][3] = As[(ar+8)*GPAD + ks*8 + tig + 4];
            }
            #pragma unroll
            for (int nt = 0; nt < 4; ++nt) {
                const int bc = wn*32 + nt*8 + g;
                const uint32_t b0 = Bs[bc*GPAD + ks*8 + tig];
                const uint32_t b1 = Bs[bc*GPAD + ks*8 + tig + 4];
                #pragma unroll
                for (int mt = 0; mt < 4; ++mt)
                    mma_tf32(acc[mt][nt], af[mt], b0, b1);
            }
        }
    }

    const float osc = (split && z == 0) ? QSCALE : 1.0f;
    #pragma unroll
    for (int mt = 0; mt < 4; ++mt) {
        #pragma unroll
        for (int nt = 0; nt < 4; ++nt) {
            const int n  = n0 + wn*32 + nt*8 + 2*tig;
            const float2 bb = *(const float2*)&bias[n];
            const int r0 = m0 + wm*64 + mt*16 + g;
            float2 v0, v1;
            v0.x = acc[mt][nt][0] + bb.x;  v0.y = acc[mt][nt][1] + bb.y;
            v1.x = acc[mt][nt][2] + bb.x;  v1.y = acc[mt][nt][3] + bb.y;
            if (split) {
                uint2 u0 = make_uint2(cvt_tf32(v0.x * osc), cvt_tf32(v0.y * osc));
                uint2 u1 = make_uint2(cvt_tf32(v1.x * osc), cvt_tf32(v1.y * osc));
                const int h = n >> 6, d = n & (DK-1);
                const int b0_ = r0 >> 11, s0_ = r0 & (SEQ-1);
                *(uint2*)&out[(((size_t)(b0_*NHEAD + h))*SEQ + s0_)*DK + d] = u0;
                const int r1 = r0 + 8;
                const int b1_ = r1 >> 11, s1_ = r1 & (SEQ-1);
                *(uint2*)&out[(((size_t)(b1_*NHEAD + h))*SEQ + s1_)*DK + d] = u1;
            } else {
                *(float2*)&out[(size_t)r0 * D_MODEL + n] = v0;
                *(float2*)&out[(size_t)(r0+8) * D_MODEL + n] = v1;
            }
        }
    }
}

// ============================================================
// Flash v3: Br=128, Bc=64, warp-local softmax, P in regs (quad shuffle),
// K/V double-buffered cp.async. Inputs pre-rounded (Q pre-scaled).
// smem: Qs[128][68] | stage{0,1}: Ks[64][68], Vs[64][72]  = 106496 B
// ============================================================
#define FQ 68
#define FV 72
#define KVSTG (64*FQ + 64*FV)                 // words per stage
#define FLASH_SMEM ((128*FQ + 2*KVSTG) * 4)   // 106496 B

__global__ __launch_bounds__(256, 2) void flash_mma(
    const float* __restrict__ Q, const float* __restrict__ K,
    const float* __restrict__ V, float* __restrict__ C)
{
    extern __shared__ uint32_t su[];
    const uint32_t sbase = smem_u32(su);
    uint32_t* Qs = su;                    // [128][FQ]

    const int tid = threadIdx.x;
    const int w   = tid >> 5;
    const int lane = tid & 31;
    const int g   = lane >> 2;
    const int tig = lane & 3;
    const int q0  = blockIdx.x * 128;
    const int bh  = blockIdx.y;

    const float* Qb = Q + ((size_t)bh*SEQ + q0)*DK;
    const float* Kb = K + (size_t)bh*SEQ*DK;
    const float* Vb = V + (size_t)bh*SEQ*DK;

    // prologue: stage Q (2048 float4 slots, 8/thread) + KV stage 0
    #pragma unroll
    for (int i = 0; i < 8; ++i) {
        const int fidx = tid + 256*i;
        const int r = fidx >> 4, col = (fidx & 15) * 4;
        CP16(sbase + (uint32_t)(r*FQ + col)*4, Qb + (size_t)r*DK + col);
    }
    {
        const uint32_t kbase = sbase + (uint32_t)(128*FQ)*4;
        #pragma unroll
        for (int i = 0; i < 4; ++i) {
            const int fidx = tid + 256*i;
            const int r = fidx >> 4, col = (fidx & 15) * 4;
            CP16(kbase + (uint32_t)(r*FQ + col)*4, Kb + (size_t)r*DK + col);
            CP16(kbase + (uint32_t)(64*FQ + r*FV + col)*4, Vb + (size_t)r*DK + col);
        }
    }
    CPCOMMIT();

    const int row0 = w*16 + g;
    float m0r = -1e30f, m1r = -1e30f, l0r = 0.f, l1r = 0.f;
    float acc[8][4];
    #pragma unroll
    for (int nt = 0; nt < 8; ++nt)
        #pragma unroll
        for (int q = 0; q < 4; ++q) acc[nt][q] = 0.f;

    for (int t = 0; t < SEQ/64; ++t) {
        CPWAIT0();
        __syncthreads();
        if (t < SEQ/64 - 1) {
            const uint32_t kbase = sbase
                + (uint32_t)(128*FQ + ((t+1) & 1) * KVSTG) * 4;
            const float* Kn = Kb + (size_t)(t+1)*64*DK;
            const float* Vn = Vb + (size_t)(t+1)*64*DK;
            #pragma unroll
            for (int i = 0; i < 4; ++i) {
                const int fidx = tid + 256*i;
                const int r = fidx >> 4, col = (fidx & 15) * 4;
                CP16(kbase + (uint32_t)(r*FQ + col)*4, Kn + (size_t)r*DK + col);
                CP16(kbase + (uint32_t)(64*FQ + r*FV + col)*4, Vn + (size_t)r*DK + col);
            }
            CPCOMMIT();
        }

        const uint32_t* Ks = su + 128*FQ + (t & 1) * KVSTG;
        const uint32_t* Vs = Ks + 64*FQ;

        // ---- S = Q K^T (log2 domain), warp tile 16x64 ----
        float s[8][4];
        #pragma unroll
        for (int nt = 0; nt < 8; ++nt)
            #pragma unroll
            for (int q = 0; q < 4; ++q) s[nt][q] = 0.f;
        #pragma unroll
        for (int ks = 0; ks < 8; ++ks) {
            uint32_t a[4];
            a[0] = Qs[row0*FQ     + ks*8 + tig];
            a[1] = Qs[(row0+8)*FQ + ks*8 + tig];
            a[2] = Qs[row0*FQ     + ks*8 + tig + 4];
            a[3] = Qs[(row0+8)*FQ + ks*8 + tig + 4];
            #pragma unroll
            for (int nt = 0; nt < 8; ++nt) {
                const int bc = nt*8 + g;
                mma_tf32(s[nt], a,
                         Ks[bc*FQ + ks*8 + tig],
                         Ks[bc*FQ + ks*8 + tig + 4]);
            }
        }

        // ---- warp-local online softmax (base 2) ----
        float mx0 = -1e30f, mx1 = -1e30f;
        #pragma unroll
        for (int nt = 0; nt < 8; ++nt) {
            mx0 = fmaxf(mx0, fmaxf(s[nt][0], s[nt][1]));
            mx1 = fmaxf(mx1, fmaxf(s[nt][2], s[nt][3]));
        }
        mx0 = fmaxf(mx0, __shfl_xor_sync(0xffffffffu, mx0, 1));
        mx0 = fmaxf(mx0, __shfl_xor_sync(0xffffffffu, mx0, 2));
        mx1 = fmaxf(mx1, __shfl_xor_sync(0xffffffffu, mx1, 1));
        mx1 = fmaxf(mx1, __shfl_xor_sync(0xffffffffu, mx1, 2));
        const float mn0 = fmaxf(m0r, mx0);
        const float mn1 = fmaxf(m1r, mx1);
        const float cr0 = ex2(m0r - mn0);
        const float cr1 = ex2(m1r - mn1);

        float sum0 = 0.f, sum1 = 0.f;
        #pragma unroll
        for (int nt = 0; nt < 8; ++nt) {
            s[nt][0] = ex2(s[nt][0] - mn0);
            s[nt][1] = ex2(s[nt][1] - mn0);
            s[nt][2] = ex2(s[nt][2] - mn1);
            s[nt][3] = ex2(s[nt][3] - mn1);
            sum0 += s[nt][0] + s[nt][1];
            sum1 += s[nt][2] + s[nt][3];
        }
        sum0 += __shfl_xor_sync(0xffffffffu, sum0, 1);
        sum0 += __shfl_xor_sync(0xffffffffu, sum0, 2);
        sum1 += __shfl_xor_sync(0xffffffffu, sum1, 1);
        sum1 += __shfl_xor_sync(0xffffffffu, sum1, 2);
        l0r = l0r * cr0 + sum0;
        l1r = l1r * cr1 + sum1;
        m0r = mn0;  m1r = mn1;

        #pragma unroll
        for (int nt = 0; nt < 8; ++nt) {
            acc[nt][0] *= cr0;  acc[nt][1] *= cr0;
            acc[nt][2] *= cr1;  acc[nt][3] *= cr1;
        }

        // ---- O += P V: permute P frags via quad shuffles ----
        const int l1 = (lane & ~3) | (tig >> 1);
        const int l2 = l1 + 2;
        const bool odd = (tig & 1);
        #pragma unroll
        for (int ks = 0; ks < 8; ++ks) {
            float b0v = __shfl_sync(0xffffffffu, s[ks][0], l1);
            float b1v = __shfl_sync(0xffffffffu, s[ks][1], l1);
            float c0v = __shfl_sync(0xffffffffu, s[ks][2], l1);
            float c1v = __shfl_sync(0xffffffffu, s[ks][3], l1);
            float d0v = __shfl_sync(0xffffffffu, s[ks][0], l2);
            float d1v = __shfl_sync(0xffffffffu, s[ks][1], l2);
            float e0v = __shfl_sync(0xffffffffu, s[ks][2], l2);
            float e1v = __shfl_sync(0xffffffffu, s[ks][3], l2);
            uint32_t a[4];
            a[0] = __float_as_uint(odd ? b1v : b0v);
            a[1] = __float_as_uint(odd ? c1v : c0v);
            a[2] = __float_as_uint(odd ? d1v : d0v);
            a[3] = __float_as_uint(odd ? e1v : e0v);
            #pragma unroll
            for (int nt = 0; nt < 8; ++nt) {
                mma_tf32(acc[nt], a,
                         Vs[(ks*8 + tig)*FV     + nt*8 + g],
                         Vs[(ks*8 + tig + 4)*FV + nt*8 + g]);
            }
        }
    }

    // epilogue: write tf32-rounded combined (feeds O-projection raw)
    const int b = bh >> 4;
    const int h = bh & 15;
    const float inv0 = 1.f / l0r;
    const float inv1 = 1.f / l1r;
    const int r0g = q0 + row0;
    #pragma unroll
    for (int nt = 0; nt < 8; ++nt) {
        const int col = h*DK + nt*8 + 2*tig;
        uint2 u0 = make_uint2(cvt_tf32(acc[nt][0] * inv0),
                              cvt_tf32(acc[nt][1] * inv0));
        uint2 u1 = make_uint2(cvt_tf32(acc[nt][2] * inv1),
                              cvt_tf32(acc[nt][3] * inv1));
        *(uint2*)&g_C[((size_t)(b*SEQ + r0g))*D_MODEL + col] = u0;
        *(uint2*)&g_C[((size_t)(b*SEQ + r0g + 8))*D_MODEL + col] = u1;
    }
    (void)C;
}

// ============================================================
// Launch
// ============================================================
extern "C" void kernel_launch(void* const* d_in, const int* in_sizes, int n_in,
                              void* d_out, int out_size)
{
    const float* query = (const float*)d_in[0];
    const float* key   = (const float*)d_in[1];
    const float* value = (const float*)d_in[2];
    const float* W_q   = (const float*)d_in[3];
    const float* b_q   = (const float*)d_in[4];
    const float* W_k   = (const float*)d_in[5];
    const float* b_k   = (const float*)d_in[6];
    const float* W_v   = (const float*)d_in[7];
    const float* b_v   = (const float*)d_in[8];
    const float* W_o   = (const float*)d_in[9];
    const float* b_o   = (const float*)d_in[10];
    float* out = (float*)d_out;

    float *Qp, *Kp, *Vp, *Cp, *Xr, *Wr;
    cudaGetSymbolAddress((void**)&Qp, g_Q);
    cudaGetSymbolAddress((void**)&Kp, g_K);
    cudaGetSymbolAddress((void**)&Vp, g_V);
    cudaGetSymbolAddress((void**)&Cp, g_C);
    cudaGetSymbolAddress((void**)&Xr, g_Xr);
    cudaGetSymbolAddress((void**)&Wr, g_Wr);

    static int attr_set = 0;
    if (!attr_set) {
        cudaFuncSetAttribute(gemm_mma,
                             cudaFuncAttributeMaxDynamicSharedMemorySize,
                             GEMM_SMEM);
        cudaFuncSetAttribute(flash_mma,
                             cudaFuncAttributeMaxDynamicSharedMemorySize,
                             FLASH_SMEM);
        attr_set = 1;
    }

    dim3 bb(256);
    const size_t XN = (size_t)MROWS * D_MODEL;   // 4M floats
    const size_t WN = (size_t)D_MODEL * D_MODEL; // 1M floats

    // pre-round inputs (z=3) and weights (z=4)
    round_prep<<<dim3(1024, 3), bb>>>(query, key, value, query,
                                      Xr, Xr + XN, Xr + 2*XN, Xr, XN/4);
    round_prep<<<dim3(512, 4), bb>>>(W_q, W_k, W_v, W_o,
                                     Wr, Wr + WN, Wr + 2*WN, Wr + 3*WN, WN/4);

    // fused QKV projections
    dim3 gqkv(MROWS/128, D_MODEL/128, 3);
    gemm_mma<<<gqkv, bb, GEMM_SMEM>>>(Xr, Xr + XN, Xr + 2*XN,
                                      Wr, Wr + WN, Wr + 2*WN,
                                      b_q, b_k, b_v,
                                      Qp, Kp, Vp, 1);

    dim3 fg(SEQ/128, BATCH*NHEAD);     // (16, 32)
    flash_mma<<<fg, bb, FLASH_SMEM>>>(Qp, Kp, Vp, Cp);

    dim3 go(MROWS/128, D_MODEL/128, 1);
    gemm_mma<<<go, bb, GEMM_SMEM>>>(Cp, Cp, Cp,
                                    Wr + 3*WN, Wr + 3*WN, Wr + 3*WN,
                                    b_o, b_o, b_o,
                                    out, out, out, 0);
}

// round 7
// speedup vs baseline: 3.1262x; 1.0412x over previous
#include <cuda_runtime.h>
#include <math.h>
#include <stdint.h>

#define D_MODEL 1024
#define NHEAD   16
#define DK      64
#define BATCH   2
#define SEQ     2048
#define MROWS   (BATCH*SEQ)   // 4096

#define QSCALE (0.125f * 1.44269504088896340736f)   // 1/sqrt(dk) * log2(e)

// ---- scratch (device globals; no allocation allowed) ----
__device__ float g_Q[BATCH*NHEAD*SEQ*DK];   // [b][h][s][d] tf32, scaled
__device__ float g_K[BATCH*NHEAD*SEQ*DK];   // [b][h][s][d] tf32
__device__ float g_V[BATCH*NHEAD*SEQ*DK];   // TRANSPOSED [b][h][d][s] tf32
__device__ float g_C[MROWS*D_MODEL];        // combined, tf32
__device__ float g_Xr[3*MROWS*D_MODEL];     // rounded query/key/value
__device__ float g_Wr[4*D_MODEL*D_MODEL];   // rounded W_q/W_k/W_v/W_o

// ============================================================
// helpers
// ============================================================
__device__ __forceinline__ uint32_t smem_u32(const void* p) {
    uint32_t a;
    asm("{ .reg .u64 t; cvta.to.shared.u64 t, %1; cvt.u32.u64 %0, t; }"
        : "=r"(a) : "l"(p));
    return a;
}
__device__ __forceinline__ uint32_t cvt_tf32(float f) {
    uint32_t r;
    asm("cvt.rna.tf32.f32 %0, %1;" : "=r"(r) : "f"(f));
    return r;
}
__device__ __forceinline__ float tf32f(float f) {
    return __uint_as_float(cvt_tf32(f));
}
__device__ __forceinline__ float ex2(float x) {
    float r;
    asm("ex2.approx.f32 %0, %1;" : "=f"(r) : "f"(x));
    return r;
}
#define CP16(dst, src) \
    asm volatile("cp.async.cg.shared.global [%0], [%1], 16;" \
                 :: "r"(dst), "l"(src) : "memory")
#define CPCOMMIT() asm volatile("cp.async.commit_group;" ::: "memory")
#define CPWAIT0()  asm volatile("cp.async.wait_group 0;" ::: "memory")

__device__ __forceinline__ void ldmx4(uint32_t* r, uint32_t addr) {
    asm volatile("ldmatrix.sync.aligned.m8n8.x4.shared.b16 "
                 "{%0,%1,%2,%3}, [%4];"
                 : "=r"(r[0]), "=r"(r[1]), "=r"(r[2]), "=r"(r[3])
                 : "r"(addr));
}

// D += A*B, m16n8k8 tf32
__device__ __forceinline__ void mma_tf32(float* d, const uint32_t* a,
                                         uint32_t b0, uint32_t b1) {
    asm volatile("mma.sync.aligned.m16n8k8.row.col.f32.tf32.tf32.f32 "
                 "{%0,%1,%2,%3}, {%4,%5,%6,%7}, {%8,%9}, {%0,%1,%2,%3};"
                 : "+f"(d[0]), "+f"(d[1]), "+f"(d[2]), "+f"(d[3])
                 : "r"(a[0]), "r"(a[1]), "r"(a[2]), "r"(a[3]),
                   "r"(b0), "r"(b1));
}

// ============================================================
// pre-round pass
// ============================================================
__global__ __launch_bounds__(256) void round_prep(
    const float* __restrict__ s0, const float* __restrict__ s1,
    const float* __restrict__ s2, const float* __restrict__ s3,
    float* __restrict__ d0, float* __restrict__ d1,
    float* __restrict__ d2, float* __restrict__ d3, int n4)
{
    const int z = blockIdx.y;
    const float4* s = (const float4*)((z == 0) ? s0 : (z == 1) ? s1
                                    : (z == 2) ? s2 : s3);
    uint4* d = (uint4*)((z == 0) ? d0 : (z == 1) ? d1 : (z == 2) ? d2 : d3);
    for (int i = blockIdx.x * blockDim.x + threadIdx.x; i < n4;
         i += gridDim.x * blockDim.x) {
        float4 v = s[i];
        d[i] = make_uint4(cvt_tf32(v.x), cvt_tf32(v.y),
                          cvt_tf32(v.z), cvt_tf32(v.w));
    }
}

// ============================================================
// GEMM v4: out = A @ W^T + bias, ldmatrix fragment loads.
// CTA 128x128, BK=32, 8 warps (2x4), warp tile 64x32.
// split: z==0 -> Q scaled split-head; z==1 -> K split-head;
//        z==2 -> V TRANSPOSED [b][h][d][s]; split==0 -> row-major.
// ============================================================
#define GPAD 36
#define GSTG (128*GPAD)            // uint32 per operand stage
#define GEMM_SMEM (4*GSTG*4)       // 73728 B

__global__ __launch_bounds__(256, 2) void gemm_mma(
    const float* __restrict__ A0, const float* __restrict__ A1,
    const float* __restrict__ A2,
    const float* __restrict__ W0, const float* __restrict__ W1,
    const float* __restrict__ W2,
    const float* __restrict__ bias0, const float* __restrict__ bias1,
    const float* __restrict__ bias2,
    float* __restrict__ O0, float* __restrict__ O1, float* __restrict__ O2,
    int split)
{
    extern __shared__ uint32_t su[];
    const uint32_t sbase = smem_u32(su);

    const int z = blockIdx.z;
    const float* A    = (z == 0) ? A0 : (z == 1) ? A1 : A2;
    const float* W    = (z == 0) ? W0 : (z == 1) ? W1 : W2;
    const float* bias = (z == 0) ? bias0 : (z == 1) ? bias1 : bias2;
    float* out        = (z == 0) ? O0 : (z == 1) ? O1 : O2;

    const int tid = threadIdx.x;
    const int w   = tid >> 5;
    const int lane = tid & 31;
    const int g   = lane >> 2;
    const int tig = lane & 3;
    const int wm  = w >> 2;
    const int wn  = w & 3;
    const int m0  = blockIdx.x * 128;
    const int n0  = blockIdx.y * 128;

    const int lr  = tid >> 1;
    const int lc0 = (tid & 1) * 16;
    const float* Ag = A + (size_t)(m0 + lr) * D_MODEL + lc0;
    const float* Wg = W + (size_t)(n0 + lr) * D_MODEL + lc0;
    const uint32_t dA = sbase + (uint32_t)(lr*GPAD + lc0) * 4;
    const uint32_t dB = dA + GSTG*4;

    // ldmatrix per-lane bases
    const int lrow_a = lane & 15;
    const int lcol_a = (lane >> 4) << 2;          // 0 or 4
    const int lrow_b = (lane & 7) | ((lane >> 4) << 3);
    const int lcol_b = ((lane >> 3) & 1) << 2;    // 0 or 4
    const uint32_t abase = sbase
        + (uint32_t)((wm*64 + lrow_a)*GPAD + lcol_a) * 4;
    const uint32_t bbase = sbase + GSTG*4
        + (uint32_t)((wn*32 + lrow_b)*GPAD + lcol_b) * 4;

    float acc[4][4][4];
    #pragma unroll
    for (int mt = 0; mt < 4; ++mt)
        #pragma unroll
        for (int nt = 0; nt < 4; ++nt)
            #pragma unroll
            for (int q = 0; q < 4; ++q) acc[mt][nt][q] = 0.f;

    #pragma unroll
    for (int i = 0; i < 4; ++i) {
        CP16(dA + 16*i, Ag + 4*i);
        CP16(dB + 16*i, Wg + 4*i);
    }
    CPCOMMIT();

    for (int c = 0; c < 32; ++c) {
        CPWAIT0();
        __syncthreads();
        if (c < 31) {
            const int k0 = (c+1) * 32;
            const uint32_t boff = (uint32_t)(((c+1) & 1) * 2*GSTG) * 4;
            #pragma unroll
            for (int i = 0; i < 4; ++i) {
                CP16(dA + boff + 16*i, Ag + k0 + 4*i);
                CP16(dB + boff + 16*i, Wg + k0 + 4*i);
            }
            CPCOMMIT();
        }

        const uint32_t boff = (uint32_t)((c & 1) * 2*GSTG) * 4;
        #pragma unroll
        for (int ks = 0; ks < 4; ++ks) {
            uint32_t af[4][4];
            #pragma unroll
            for (int mt = 0; mt < 4; ++mt)
                ldmx4(af[mt], abase + boff
                      + (uint32_t)(mt*16*GPAD)*4 + ks*32);
            #pragma unroll
            for (int p = 0; p < 2; ++p) {
                uint32_t bf[4];
                ldmx4(bf, bbase + boff + (uint32_t)(p*16*GPAD)*4 + ks*32);
                #pragma unroll
                for (int mt = 0; mt < 4; ++mt) {
                    mma_tf32(acc[mt][2*p],   af[mt], bf[0], bf[1]);
                    mma_tf32(acc[mt][2*p+1], af[mt], bf[2], bf[3]);
                }
            }
        }
    }

    const float osc = (split && z == 0) ? QSCALE : 1.0f;
    #pragma unroll
    for (int mt = 0; mt < 4; ++mt) {
        #pragma unroll
        for (int nt = 0; nt < 4; ++nt) {
            const int n  = n0 + wn*32 + nt*8 + 2*tig;
            const float2 bb = *(const float2*)&bias[n];
            const int r0 = m0 + wm*64 + mt*16 + g;
            float2 v0, v1;
            v0.x = acc[mt][nt][0] + bb.x;  v0.y = acc[mt][nt][1] + bb.y;
            v1.x = acc[mt][nt][2] + bb.x;  v1.y = acc[mt][nt][3] + bb.y;
            if (split) {
                const int h = n >> 6, d = n & (DK-1);
                const int b0_ = r0 >> 11, s0_ = r0 & (SEQ-1);
                const int r1 = r0 + 8;
                const int b1_ = r1 >> 11, s1_ = r1 & (SEQ-1);
                if (z == 2) {
                    // transposed V: [b][h][d][s]
                    const size_t h0 = (size_t)(b0_*NHEAD + h) * DK;
                    const size_t h1 = (size_t)(b1_*NHEAD + h) * DK;
                    out[(h0 + d)*SEQ + s0_]     = tf32f(v0.x);
                    out[(h0 + d + 1)*SEQ + s0_] = tf32f(v0.y);
                    out[(h1 + d)*SEQ + s1_]     = tf32f(v1.x);
                    out[(h1 + d + 1)*SEQ + s1_] = tf32f(v1.y);
                } else {
                    uint2 u0 = make_uint2(cvt_tf32(v0.x * osc),
                                          cvt_tf32(v0.y * osc));
                    uint2 u1 = make_uint2(cvt_tf32(v1.x * osc),
                                          cvt_tf32(v1.y * osc));
                    *(uint2*)&out[(((size_t)(b0_*NHEAD + h))*SEQ + s0_)*DK + d] = u0;
                    *(uint2*)&out[(((size_t)(b1_*NHEAD + h))*SEQ + s1_)*DK + d] = u1;
                }
            } else {
                *(float2*)&out[(size_t)r0 * D_MODEL + n] = v0;
                *(float2*)&out[(size_t)(r0+8) * D_MODEL + n] = v1;
            }
        }
    }
}

// ============================================================
// Flash v4: Br=128, Bc=64, ldmatrix fragments, V transposed.
// smem: Qs[128][68] | stage{0,1}: Ks[64][68] + Vts[64][68]
// ============================================================
#define FQ 68
#define KVSTG (2*64*FQ)                       // words per stage (K + Vt)
#define FLASH_SMEM ((128*FQ + 2*KVSTG) * 4)   // 104448 B

__global__ __launch_bounds__(256, 2) void flash_mma(
    const float* __restrict__ Q, const float* __restrict__ K,
    const float* __restrict__ Vt, float* __restrict__ C)
{
    extern __shared__ uint32_t su[];
    const uint32_t sbase = smem_u32(su);

    const int tid = threadIdx.x;
    const int w   = tid >> 5;
    const int lane = tid & 31;
    const int g   = lane >> 2;
    const int tig = lane & 3;
    const int q0  = blockIdx.x * 128;
    const int bh  = blockIdx.y;

    const float* Qb  = Q + ((size_t)bh*SEQ + q0)*DK;
    const float* Kb  = K + (size_t)bh*SEQ*DK;
    const float* Vtb = Vt + (size_t)bh*DK*SEQ;

    // prologue: stage Q + KV stage 0
    #pragma unroll
    for (int i = 0; i < 8; ++i) {
        const int fidx = tid + 256*i;
        const int r = fidx >> 4, col = (fidx & 15) * 4;
        CP16(sbase + (uint32_t)(r*FQ + col)*4, Qb + (size_t)r*DK + col);
    }
    {
        const uint32_t kb = sbase + (uint32_t)(128*FQ)*4;
        #pragma unroll
        for (int i = 0; i < 4; ++i) {
            const int fidx = tid + 256*i;
            const int r = fidx >> 4, col = (fidx & 15) * 4;
            CP16(kb + (uint32_t)(r*FQ + col)*4, Kb + (size_t)r*DK + col);
            CP16(kb + (uint32_t)(64*FQ + r*FQ + col)*4,
                 Vtb + (size_t)r*SEQ + col);
        }
    }
    CPCOMMIT();

    // ldmatrix per-lane bases
    const int lrow_a = lane & 15;
    const int lcol_a = (lane >> 4) << 2;
    const int lrow_b = (lane & 7) | ((lane >> 4) << 3);
    const int lcol_b = ((lane >> 3) & 1) << 2;
    const uint32_t q_lm = sbase
        + (uint32_t)((w*16 + lrow_a)*FQ + lcol_a) * 4;
    const uint32_t b_lmoff = (uint32_t)(lrow_b*FQ + lcol_b) * 4;

    const int row0 = w*16 + g;
    float m0r = -1e30f, m1r = -1e30f, l0r = 0.f, l1r = 0.f;
    float acc[8][4];
    #pragma unroll
    for (int nt = 0; nt < 8; ++nt)
        #pragma unroll
        for (int q = 0; q < 4; ++q) acc[nt][q] = 0.f;

    for (int t = 0; t < SEQ/64; ++t) {
        CPWAIT0();
        __syncthreads();
        if (t < SEQ/64 - 1) {
            const uint32_t kb = sbase
                + (uint32_t)(128*FQ + ((t+1) & 1) * KVSTG) * 4;
            const float* Kn = Kb + (size_t)(t+1)*64*DK;
            const float* Vn = Vtb + (size_t)(t+1)*64;
            #pragma unroll
            for (int i = 0; i < 4; ++i) {
                const int fidx = tid + 256*i;
                const int r = fidx >> 4, col = (fidx & 15) * 4;
                CP16(kb + (uint32_t)(r*FQ + col)*4, Kn + (size_t)r*DK + col);
                CP16(kb + (uint32_t)(64*FQ + r*FQ + col)*4,
                     Vn + (size_t)r*SEQ + col);
            }
            CPCOMMIT();
        }

        const uint32_t k_lm = sbase
            + (uint32_t)(128*FQ + (t & 1)*KVSTG) * 4 + b_lmoff;
        const uint32_t v_lm = k_lm + (uint32_t)(64*FQ)*4;

        // ---- S = Q K^T (log2 domain) ----
        float s[8][4];
        #pragma unroll
        for (int nt = 0; nt < 8; ++nt)
            #pragma unroll
            for (int q = 0; q < 4; ++q) s[nt][q] = 0.f;
        #pragma unroll
        for (int ks = 0; ks < 8; ++ks) {
            uint32_t qa[4];
            ldmx4(qa, q_lm + ks*32);
            #pragma unroll
            for (int p = 0; p < 4; ++p) {
                uint32_t kf[4];
                ldmx4(kf, k_lm + (uint32_t)(p*16*FQ)*4 + ks*32);
                mma_tf32(s[2*p],   qa, kf[0], kf[1]);
                mma_tf32(s[2*p+1], qa, kf[2], kf[3]);
            }
        }

        // ---- warp-local online softmax (base 2) ----
        float mx0 = -1e30f, mx1 = -1e30f;
        #pragma unroll
        for (int nt = 0; nt < 8; ++nt) {
            mx0 = fmaxf(mx0, fmaxf(s[nt][0], s[nt][1]));
            mx1 = fmaxf(mx1, fmaxf(s[nt][2], s[nt][3]));
        }
        mx0 = fmaxf(mx0, __shfl_xor_sync(0xffffffffu, mx0, 1));
        mx0 = fmaxf(mx0, __shfl_xor_sync(0xffffffffu, mx0, 2));
        mx1 = fmaxf(mx1, __shfl_xor_sync(0xffffffffu, mx1, 1));
        mx1 = fmaxf(mx1, __shfl_xor_sync(0xffffffffu, mx1, 2));
        const float mn0 = fmaxf(m0r, mx0);
        const float mn1 = fmaxf(m1r, mx1);
        const float cr0 = ex2(m0r - mn0);
        const float cr1 = ex2(m1r - mn1);

        float sum0 = 0.f, sum1 = 0.f;
        #pragma unroll
        for (int nt = 0; nt < 8; ++nt) {
            s[nt][0] = ex2(s[nt][0] - mn0);
            s[nt][1] = ex2(s[nt][1] - mn0);
            s[nt][2] = ex2(s[nt][2] - mn1);
            s[nt][3] = ex2(s[nt][3] - mn1);
            sum0 += s[nt][0] + s[nt][1];
            sum1 += s[nt][2] + s[nt][3];
        }
        sum0 += __shfl_xor_sync(0xffffffffu, sum0, 1);
        sum0 += __shfl_xor_sync(0xffffffffu, sum0, 2);
        sum1 += __shfl_xor_sync(0xffffffffu, sum1, 1);
        sum1 += __shfl_xor_sync(0xffffffffu, sum1, 2);
        l0r = l0r * cr0 + sum0;
        l1r = l1r * cr1 + sum1;
        m0r = mn0;  m1r = mn1;

        #pragma unroll
        for (int nt = 0; nt < 8; ++nt) {
            acc[nt][0] *= cr0;  acc[nt][1] *= cr0;
            acc[nt][2] *= cr1;  acc[nt][3] *= cr1;
        }

        // ---- O += P V ----
        const int l1 = (lane & ~3) | (tig >> 1);
        const int l2 = l1 + 2;
        const bool odd = (tig & 1);
        #pragma unroll
        for (int ks = 0; ks < 8; ++ks) {
            float b0v = __shfl_sync(0xffffffffu, s[ks][0], l1);
            float b1v = __shfl_sync(0xffffffffu, s[ks][1], l1);
            float c0v = __shfl_sync(0xffffffffu, s[ks][2], l1);
            float c1v = __shfl_sync(0xffffffffu, s[ks][3], l1);
            float d0v = __shfl_sync(0xffffffffu, s[ks][0], l2);
            float d1v = __shfl_sync(0xffffffffu, s[ks][1], l2);
            float e0v = __shfl_sync(0xffffffffu, s[ks][2], l2);
            float e1v = __shfl_sync(0xffffffffu, s[ks][3], l2);
            uint32_t a[4];
            a[0] = __float_as_uint(odd ? b1v : b0v);
            a[1] = __float_as_uint(odd ? c1v : c0v);
            a[2] = __float_as_uint(odd ? d1v : d0v);
            a[3] = __float_as_uint(odd ? e1v : e0v);
            #pragma unroll
            for (int p = 0; p < 4; ++p) {
                uint32_t vf[4];
                ldmx4(vf, v_lm + (uint32_t)(p*16*FQ)*4 + ks*32);
                mma_tf32(acc[2*p],   a, vf[0], vf[1]);
                mma_tf32(acc[2*p+1], a, vf[2], vf[3]);
            }
        }
    }

    // epilogue: tf32-rounded combined
    const int b = bh >> 4;
    const int h = bh & 15;
    const float inv0 = 1.f / l0r;
    const float inv1 = 1.f / l1r;
    const int r0g = q0 + row0;
    #pragma unroll
    for (int nt = 0; nt < 8; ++nt) {
        const int col = h*DK + nt*8 + 2*tig;
        uint2 u0 = make_uint2(cvt_tf32(acc[nt][0] * inv0),
                              cvt_tf32(acc[nt][1] * inv0));
        uint2 u1 = make_uint2(cvt_tf32(acc[nt][2] * inv1),
                              cvt_tf32(acc[nt][3] * inv1));
        *(uint2*)&g_C[((size_t)(b*SEQ + r0g))*D_MODEL + col] = u0;
        *(uint2*)&g_C[((size_t)(b*SEQ + r0g + 8))*D_MODEL + col] = u1;
    }
    (void)C;
}

// ============================================================
// Launch
// ============================================================
extern "C" void kernel_launch(void* const* d_in, const int* in_sizes, int n_in,
                              void* d_out, int out_size)
{
    const float* query = (const float*)d_in[0];
    const float* key   = (const float*)d_in[1];
    const float* value = (const float*)d_in[2];
    const float* W_q   = (const float*)d_in[3];
    const float* b_q   = (const float*)d_in[4];
    const float* W_k   = (const float*)d_in[5];
    const float* b_k   = (const float*)d_in[6];
    const float* W_v   = (const float*)d_in[7];
    const float* b_v   = (const float*)d_in[8];
    const float* W_o   = (const float*)d_in[9];
    const float* b_o   = (const float*)d_in[10];
    float* out = (float*)d_out;

    float *Qp, *Kp, *Vp, *Cp, *Xr, *Wr;
    cudaGetSymbolAddress((void**)&Qp, g_Q);
    cudaGetSymbolAddress((void**)&Kp, g_K);
    cudaGetSymbolAddress((void**)&Vp, g_V);
    cudaGetSymbolAddress((void**)&Cp, g_C);
    cudaGetSymbolAddress((void**)&Xr, g_Xr);
    cudaGetSymbolAddress((void**)&Wr, g_Wr);

    static int attr_set = 0;
    if (!attr_set) {
        cudaFuncSetAttribute(gemm_mma,
                             cudaFuncAttributeMaxDynamicSharedMemorySize,
                             GEMM_SMEM);
        cudaFuncSetAttribute(flash_mma,
                             cudaFuncAttributeMaxDynamicSharedMemorySize,
                             FLASH_SMEM);
        attr_set = 1;
    }

    dim3 bb(256);
    const size_t XN = (size_t)MROWS * D_MODEL;
    const size_t WN = (size_t)D_MODEL * D_MODEL;

    round_prep<<<dim3(1024, 3), bb>>>(query, key, value, query,
                                      Xr, Xr + XN, Xr + 2*XN, Xr, XN/4);
    round_prep<<<dim3(512, 4), bb>>>(W_q, W_k, W_v, W_o,
                                     Wr, Wr + WN, Wr + 2*WN, Wr + 3*WN, WN/4);

    dim3 gqkv(MROWS/128, D_MODEL/128, 3);
    gemm_mma<<<gqkv, bb, GEMM_SMEM>>>(Xr, Xr + XN, Xr + 2*XN,
                                      Wr, Wr + WN, Wr + 2*WN,
                                      b_q, b_k, b_v,
                                      Qp, Kp, Vp, 1);

    dim3 fg(SEQ/128, BATCH*NHEAD);
    flash_mma<<<fg, bb, FLASH_SMEM>>>(Qp, Kp, Vp, Cp);

    dim3 go(MROWS/128, D_MODEL/128, 1);
    gemm_mma<<<go, bb, GEMM_SMEM>>>(Cp, Cp, Cp,
                                    Wr + 3*WN, Wr + 3*WN, Wr + 3*WN,
                                    b_o, b_o, b_o,
                                    out, out, out, 0);
}

// round 8
// speedup vs baseline: 6.1014x; 1.9517x over previous
#include <cuda_runtime.h>
#include <cuda_fp16.h>
#include <math.h>
#include <stdint.h>

#define D_MODEL 1024
#define NHEAD   16
#define DK      64
#define BATCH   2
#define SEQ     2048
#define MROWS   (BATCH*SEQ)   // 4096

#define QSCALE (0.125f * 1.44269504088896340736f)   // 1/sqrt(dk) * log2(e)

// ---- scratch (device globals; fp16) ----
__device__ __half g_Q[BATCH*NHEAD*SEQ*DK];   // [b][h][s][d], scaled
__device__ __half g_K[BATCH*NHEAD*SEQ*DK];   // [b][h][s][d]
__device__ __half g_V[BATCH*NHEAD*SEQ*DK];   // TRANSPOSED [b][h][d][s]
__device__ __half g_C[MROWS*D_MODEL];        // combined [b][s][h*64+d]
__device__ __half g_Xh[3*MROWS*D_MODEL];     // fp16 query/key/value
__device__ __half g_Wh[4*D_MODEL*D_MODEL];   // fp16 W_q/W_k/W_v/W_o

// ============================================================
// helpers
// ============================================================
__device__ __forceinline__ uint32_t smem_u32(const void* p) {
    uint32_t a;
    asm("{ .reg .u64 t; cvta.to.shared.u64 t, %1; cvt.u32.u64 %0, t; }"
        : "=r"(a) : "l"(p));
    return a;
}
__device__ __forceinline__ float ex2(float x) {
    float r;
    asm("ex2.approx.f32 %0, %1;" : "=f"(r) : "f"(x));
    return r;
}
// pack {lo, hi} floats -> half2 in b32
__device__ __forceinline__ uint32_t pack_h2(float lo, float hi) {
    uint32_t r;
    asm("cvt.rn.f16x2.f32 %0, %1, %2;" : "=r"(r) : "f"(hi), "f"(lo));
    return r;
}
#define CP16(dst, src) \
    asm volatile("cp.async.cg.shared.global [%0], [%1], 16;" \
                 :: "r"(dst), "l"(src) : "memory")
#define CPCOMMIT() asm volatile("cp.async.commit_group;" ::: "memory")
#define CPWAIT0()  asm volatile("cp.async.wait_group 0;" ::: "memory")

__device__ __forceinline__ void ldmx4(uint32_t* r, uint32_t addr) {
    asm volatile("ldmatrix.sync.aligned.m8n8.x4.shared.b16 "
                 "{%0,%1,%2,%3}, [%4];"
                 : "=r"(r[0]), "=r"(r[1]), "=r"(r[2]), "=r"(r[3])
                 : "r"(addr));
}

// D += A*B, m16n8k16 fp16 with f32 accumulate
__device__ __forceinline__ void mma_f16(float* d, const uint32_t* a,
                                        uint32_t b0, uint32_t b1) {
    asm volatile("mma.sync.aligned.m16n8k16.row.col.f32.f16.f16.f32 "
                 "{%0,%1,%2,%3}, {%4,%5,%6,%7}, {%8,%9}, {%0,%1,%2,%3};"
                 : "+f"(d[0]), "+f"(d[1]), "+f"(d[2]), "+f"(d[3])
                 : "r"(a[0]), "r"(a[1]), "r"(a[2]), "r"(a[3]),
                   "r"(b0), "r"(b1));
}

// ============================================================
// prep: f32 -> f16
// ============================================================
__global__ __launch_bounds__(256) void half_prep(
    const float* __restrict__ s0, const float* __restrict__ s1,
    const float* __restrict__ s2, const float* __restrict__ s3,
    __half* __restrict__ d0, __half* __restrict__ d1,
    __half* __restrict__ d2, __half* __restrict__ d3, int n4)
{
    const int z = blockIdx.y;
    const float4* s = (const float4*)((z == 0) ? s0 : (z == 1) ? s1
                                    : (z == 2) ? s2 : s3);
    uint2* d = (uint2*)((z == 0) ? d0 : (z == 1) ? d1 : (z == 2) ? d2 : d3);
    for (int i = blockIdx.x * blockDim.x + threadIdx.x; i < n4;
         i += gridDim.x * blockDim.x) {
        float4 v = s[i];
        d[i] = make_uint2(pack_h2(v.x, v.y), pack_h2(v.z, v.w));
    }
}

// ============================================================
// GEMM fp16: out = A @ W^T + bias. CTA 128x128, BK=64, 8 warps (2x4),
// warp tile 64x32. cp.async double-buffered, ldmatrix fragments.
// split: z==0 Q scaled split-head (half); z==1 K split-head (half);
//        z==2 V transposed [b][h][d][s] (half); split==0 row-major f32.
// ============================================================
#define GPADH 72                       // halves per row
#define GOPB  (128*GPADH*2)            // bytes per operand stage (18432)
#define GSTGB (2*GOPB)                 // bytes per stage (A+B)
#define GEMM_SMEM (2*GSTGB)            // 73728 B

__global__ __launch_bounds__(256, 2) void gemm_mma(
    const __half* __restrict__ A0, const __half* __restrict__ A1,
    const __half* __restrict__ A2,
    const __half* __restrict__ W0, const __half* __restrict__ W1,
    const __half* __restrict__ W2,
    const float* __restrict__ bias0, const float* __restrict__ bias1,
    const float* __restrict__ bias2,
    void* __restrict__ O0, void* __restrict__ O1, void* __restrict__ O2,
    int split)
{
    extern __shared__ uint32_t su[];
    const uint32_t sbase = smem_u32(su);

    const int z = blockIdx.z;
    const __half* A   = (z == 0) ? A0 : (z == 1) ? A1 : A2;
    const __half* W   = (z == 0) ? W0 : (z == 1) ? W1 : W2;
    const float* bias = (z == 0) ? bias0 : (z == 1) ? bias1 : bias2;
    void* outv        = (z == 0) ? O0 : (z == 1) ? O1 : O2;

    const int tid = threadIdx.x;
    const int w    = tid >> 5;
    const int lane = tid & 31;
    const int g   = lane >> 2;
    const int tig = lane & 3;
    const int wm  = w >> 2;
    const int wn  = w & 3;
    const int m0  = blockIdx.x * 128;
    const int n0  = blockIdx.y * 128;

    // staging: 128 rows x 64 halves per operand; 8 cp16 per row;
    // thread t: row = t>>1, cols (t&1)*32 + i*8, i<4
    const int lr  = tid >> 1;
    const int lc0 = (tid & 1) * 32;
    const __half* Ag = A + (size_t)(m0 + lr) * D_MODEL + lc0;
    const __half* Wg = W + (size_t)(n0 + lr) * D_MODEL + lc0;
    const uint32_t dsm = (uint32_t)(lr*GPADH + lc0) * 2;

    // ldmatrix lane bases
    const int row_a = (lane & 7) + (((lane >> 3) & 1) << 3);
    const int col_a = (lane >> 4) << 3;
    const int row_b = (lane & 7) + ((lane >> 4) << 3);
    const int col_b = ((lane >> 3) & 1) << 3;
    const uint32_t a_lm = (uint32_t)((wm*64 + row_a)*GPADH + col_a) * 2;
    const uint32_t b_lm = (uint32_t)(GOPB)
        + (uint32_t)((wn*32 + row_b)*GPADH + col_b) * 2;

    float acc[4][4][4];
    #pragma unroll
    for (int mt = 0; mt < 4; ++mt)
        #pragma unroll
        for (int nt = 0; nt < 4; ++nt)
            #pragma unroll
            for (int q = 0; q < 4; ++q) acc[mt][nt][q] = 0.f;

    // prologue: chunk 0 -> stage 0
    #pragma unroll
    for (int i = 0; i < 4; ++i) {
        CP16(sbase + dsm + 16*i, Ag + 8*i);
        CP16(sbase + GOPB + dsm + 16*i, Wg + 8*i);
    }
    CPCOMMIT();

    for (int c = 0; c < 16; ++c) {
        CPWAIT0();
        __syncthreads();
        if (c < 15) {
            const int k0 = (c+1) * 64;
            const uint32_t stg = sbase + (uint32_t)(((c+1) & 1) * GSTGB);
            #pragma unroll
            for (int i = 0; i < 4; ++i) {
                CP16(stg + dsm + 16*i, Ag + k0 + 8*i);
                CP16(stg + GOPB + dsm + 16*i, Wg + k0 + 8*i);
            }
            CPCOMMIT();
        }

        const uint32_t stg = sbase + (uint32_t)((c & 1) * GSTGB);
        #pragma unroll
        for (int ks = 0; ks < 4; ++ks) {
            uint32_t af[4][4];
            #pragma unroll
            for (int mt = 0; mt < 4; ++mt)
                ldmx4(af[mt], stg + a_lm
                      + (uint32_t)(mt*16*GPADH)*2 + ks*32);
            #pragma unroll
            for (int p = 0; p < 2; ++p) {
                uint32_t bf[4];
                ldmx4(bf, stg + b_lm + (uint32_t)(p*16*GPADH)*2 + ks*32);
                #pragma unroll
                for (int mt = 0; mt < 4; ++mt) {
                    mma_f16(acc[mt][2*p],   af[mt], bf[0], bf[1]);
                    mma_f16(acc[mt][2*p+1], af[mt], bf[2], bf[3]);
                }
            }
        }
    }

    const float osc = (split && z == 0) ? QSCALE : 1.0f;
    #pragma unroll
    for (int mt = 0; mt < 4; ++mt) {
        #pragma unroll
        for (int nt = 0; nt < 4; ++nt) {
            const int n  = n0 + wn*32 + nt*8 + 2*tig;
            const float2 bb = *(const float2*)&bias[n];
            const int r0 = m0 + wm*64 + mt*16 + g;
            float2 v0, v1;
            v0.x = acc[mt][nt][0] + bb.x;  v0.y = acc[mt][nt][1] + bb.y;
            v1.x = acc[mt][nt][2] + bb.x;  v1.y = acc[mt][nt][3] + bb.y;
            if (split) {
                __half* out = (__half*)outv;
                const int h = n >> 6, d = n & (DK-1);
                const int b0_ = r0 >> 11, s0_ = r0 & (SEQ-1);
                const int r1 = r0 + 8;
                const int b1_ = r1 >> 11, s1_ = r1 & (SEQ-1);
                if (z == 2) {
                    const size_t h0 = (size_t)(b0_*NHEAD + h) * DK;
                    const size_t h1 = (size_t)(b1_*NHEAD + h) * DK;
                    out[(h0 + d)*SEQ + s0_]     = __float2half_rn(v0.x);
                    out[(h0 + d + 1)*SEQ + s0_] = __float2half_rn(v0.y);
                    out[(h1 + d)*SEQ + s1_]     = __float2half_rn(v1.x);
                    out[(h1 + d + 1)*SEQ + s1_] = __float2half_rn(v1.y);
                } else {
                    uint32_t u0 = pack_h2(v0.x * osc, v0.y * osc);
                    uint32_t u1 = pack_h2(v1.x * osc, v1.y * osc);
                    *(uint32_t*)&out[(((size_t)(b0_*NHEAD + h))*SEQ + s0_)*DK + d] = u0;
                    *(uint32_t*)&out[(((size_t)(b1_*NHEAD + h))*SEQ + s1_)*DK + d] = u1;
                }
            } else {
                float* out = (float*)outv;
                *(float2*)&out[(size_t)r0 * D_MODEL + n] = v0;
                *(float2*)&out[(size_t)(r0+8) * D_MODEL + n] = v1;
            }
        }
    }
}

// ============================================================
// Flash fp16: Br=128, Bc=64. S and PV via m16n8k16; P converts from
// S-accumulator directly into A fragments (no shuffles, no smem P).
// smem: Q[128][72]h | stage{0,1}: K[64][72]h + Vt[64][72]h = 55296 B
// ============================================================
#define FOPB (64*GPADH*2)                  // 9216 B (one 64-row tensor)
#define KVSTGB (2*FOPB)                    // 18432 B per stage
#define FQB (128*GPADH*2)                  // 18432 B (Q)
#define FLASH_SMEM (FQB + 2*KVSTGB)        // 55296 B

__global__ __launch_bounds__(256, 3) void flash_mma(
    const __half* __restrict__ Q, const __half* __restrict__ K,
    const __half* __restrict__ Vt, __half* __restrict__ C)
{
    extern __shared__ uint32_t su[];
    const uint32_t sbase = smem_u32(su);

    const int tid = threadIdx.x;
    const int w    = tid >> 5;
    const int lane = tid & 31;
    const int g   = lane >> 2;
    const int tig = lane & 3;
    const int q0  = blockIdx.x * 128;
    const int bh  = blockIdx.y;

    const __half* Qb  = Q + ((size_t)bh*SEQ + q0)*DK;
    const __half* Kb  = K + (size_t)bh*SEQ*DK;
    const __half* Vtb = Vt + (size_t)bh*DK*SEQ;

    // prologue: Q (1024 cp16, 4/thread) + KV stage 0 (512 each, 2/thread)
    #pragma unroll
    for (int i = 0; i < 4; ++i) {
        const int fidx = tid + 256*i;
        const int r = fidx >> 3, ch = (fidx & 7) * 8;
        CP16(sbase + (uint32_t)(r*GPADH + ch)*2, Qb + (size_t)r*DK + ch);
    }
    #pragma unroll
    for (int i = 0; i < 2; ++i) {
        const int fidx = tid + 256*i;
        const int r = fidx >> 3, ch = (fidx & 7) * 8;
        CP16(sbase + FQB + (uint32_t)(r*GPADH + ch)*2,
             Kb + (size_t)r*DK + ch);
        CP16(sbase + FQB + FOPB + (uint32_t)(r*GPADH + ch)*2,
             Vtb + (size_t)r*SEQ + ch);
    }
    CPCOMMIT();

    // ldmatrix lane bases
    const int row_a = (lane & 7) + (((lane >> 3) & 1) << 3);
    const int col_a = (lane >> 4) << 3;
    const int row_b = (lane & 7) + ((lane >> 4) << 3);
    const int col_b = ((lane >> 3) & 1) << 3;
    const uint32_t q_lm = sbase + (uint32_t)((w*16 + row_a)*GPADH + col_a)*2;
    const uint32_t b_lmo = (uint32_t)(row_b*GPADH + col_b)*2;

    float m0r = -1e30f, m1r = -1e30f, l0r = 0.f, l1r = 0.f;
    float acc[8][4];
    #pragma unroll
    for (int nt = 0; nt < 8; ++nt)
        #pragma unroll
        for (int q = 0; q < 4; ++q) acc[nt][q] = 0.f;

    for (int t = 0; t < SEQ/64; ++t) {
        CPWAIT0();
        __syncthreads();
        if (t < SEQ/64 - 1) {
            const uint32_t stg = sbase + FQB + (uint32_t)(((t+1) & 1)*KVSTGB);
            const __half* Kn = Kb + (size_t)(t+1)*64*DK;
            const __half* Vn = Vtb + (size_t)(t+1)*64;
            #pragma unroll
            for (int i = 0; i < 2; ++i) {
                const int fidx = tid + 256*i;
                const int r = fidx >> 3, ch = (fidx & 7) * 8;
                CP16(stg + (uint32_t)(r*GPADH + ch)*2,
                     Kn + (size_t)r*DK + ch);
                CP16(stg + FOPB + (uint32_t)(r*GPADH + ch)*2,
                     Vn + (size_t)r*SEQ + ch);
            }
            CPCOMMIT();
        }

        const uint32_t k_lm = sbase + FQB + (uint32_t)((t & 1)*KVSTGB) + b_lmo;
        const uint32_t v_lm = k_lm + FOPB;

        // ---- S = Q K^T (log2 domain) ----
        float s[8][4];
        #pragma unroll
        for (int nt = 0; nt < 8; ++nt)
            #pragma unroll
            for (int q = 0; q < 4; ++q) s[nt][q] = 0.f;
        #pragma unroll
        for (int ks = 0; ks < 4; ++ks) {
            uint32_t qa[4];
            ldmx4(qa, q_lm + ks*32);
            #pragma unroll
            for (int p = 0; p < 4; ++p) {
                uint32_t kf[4];
                ldmx4(kf, k_lm + (uint32_t)(p*16*GPADH)*2 + ks*32);
                mma_f16(s[2*p],   qa, kf[0], kf[1]);
                mma_f16(s[2*p+1], qa, kf[2], kf[3]);
            }
        }

        // ---- warp-local online softmax (base 2) ----
        float mx0 = -1e30f, mx1 = -1e30f;
        #pragma unroll
        for (int nt = 0; nt < 8; ++nt) {
            mx0 = fmaxf(mx0, fmaxf(s[nt][0], s[nt][1]));
            mx1 = fmaxf(mx1, fmaxf(s[nt][2], s[nt][3]));
        }
        mx0 = fmaxf(mx0, __shfl_xor_sync(0xffffffffu, mx0, 1));
        mx0 = fmaxf(mx0, __shfl_xor_sync(0xffffffffu, mx0, 2));
        mx1 = fmaxf(mx1, __shfl_xor_sync(0xffffffffu, mx1, 1));
        mx1 = fmaxf(mx1, __shfl_xor_sync(0xffffffffu, mx1, 2));
        const float mn0 = fmaxf(m0r, mx0);
        const float mn1 = fmaxf(m1r, mx1);
        const float cr0 = ex2(m0r - mn0);
        const float cr1 = ex2(m1r - mn1);

        float sum0 = 0.f, sum1 = 0.f;
        #pragma unroll
        for (int nt = 0; nt < 8; ++nt) {
            s[nt][0] = ex2(s[nt][0] - mn0);
            s[nt][1] = ex2(s[nt][1] - mn0);
            s[nt][2] = ex2(s[nt][2] - mn1);
            s[nt][3] = ex2(s[nt][3] - mn1);
            sum0 += s[nt][0] + s[nt][1];
            sum1 += s[nt][2] + s[nt][3];
        }
        sum0 += __shfl_xor_sync(0xffffffffu, sum0, 1);
        sum0 += __shfl_xor_sync(0xffffffffu, sum0, 2);
        sum1 += __shfl_xor_sync(0xffffffffu, sum1, 1);
        sum1 += __shfl_xor_sync(0xffffffffu, sum1, 2);
        l0r = l0r * cr0 + sum0;
        l1r = l1r * cr1 + sum1;
        m0r = mn0;  m1r = mn1;

        #pragma unroll
        for (int nt = 0; nt < 8; ++nt) {
            acc[nt][0] *= cr0;  acc[nt][1] *= cr0;
            acc[nt][2] *= cr1;  acc[nt][3] *= cr1;
        }

        // ---- O += P V: P acc -> fp16 A frags directly ----
        #pragma unroll
        for (int j = 0; j < 4; ++j) {
            uint32_t a[4];
            a[0] = pack_h2(s[2*j][0],   s[2*j][1]);
            a[1] = pack_h2(s[2*j][2],   s[2*j][3]);
            a[2] = pack_h2(s[2*j+1][0], s[2*j+1][1]);
            a[3] = pack_h2(s[2*j+1][2], s[2*j+1][3]);
            #pragma unroll
            for (int p = 0; p < 4; ++p) {
                uint32_t vf[4];
                ldmx4(vf, v_lm + (uint32_t)(p*16*GPADH)*2 + j*32);
                mma_f16(acc[2*p],   a, vf[0], vf[1]);
                mma_f16(acc[2*p+1], a, vf[2], vf[3]);
            }
        }
    }

    // epilogue: half combined [b][s][h*64+d]
    const int b = bh >> 4;
    const int h = bh & 15;
    const float inv0 = 1.f / l0r;
    const float inv1 = 1.f / l1r;
    const int r0g = q0 + w*16 + g;
    #pragma unroll
    for (int nt = 0; nt < 8; ++nt) {
        const int col = h*DK + nt*8 + 2*tig;
        uint32_t u0 = pack_h2(acc[nt][0] * inv0, acc[nt][1] * inv0);
        uint32_t u1 = pack_h2(acc[nt][2] * inv1, acc[nt][3] * inv1);
        *(uint32_t*)&C[((size_t)(b*SEQ + r0g))*D_MODEL + col] = u0;
        *(uint32_t*)&C[((size_t)(b*SEQ + r0g + 8))*D_MODEL + col] = u1;
    }
}

// ============================================================
// Launch
// ============================================================
extern "C" void kernel_launch(void* const* d_in, const int* in_sizes, int n_in,
                              void* d_out, int out_size)
{
    const float* query = (const float*)d_in[0];
    const float* key   = (const float*)d_in[1];
    const float* value = (const float*)d_in[2];
    const float* W_q   = (const float*)d_in[3];
    const float* b_q   = (const float*)d_in[4];
    const float* W_k   = (const float*)d_in[5];
    const float* b_k   = (const float*)d_in[6];
    const float* W_v   = (const float*)d_in[7];
    const float* b_v   = (const float*)d_in[8];
    const float* W_o   = (const float*)d_in[9];
    const float* b_o   = (const float*)d_in[10];
    float* out = (float*)d_out;

    __half *Qp, *Kp, *Vp, *Cp, *Xh, *Wh;
    cudaGetSymbolAddress((void**)&Qp, g_Q);
    cudaGetSymbolAddress((void**)&Kp, g_K);
    cudaGetSymbolAddress((void**)&Vp, g_V);
    cudaGetSymbolAddress((void**)&Cp, g_C);
    cudaGetSymbolAddress((void**)&Xh, g_Xh);
    cudaGetSymbolAddress((void**)&Wh, g_Wh);

    static int attr_set = 0;
    if (!attr_set) {
        cudaFuncSetAttribute(gemm_mma,
                             cudaFuncAttributeMaxDynamicSharedMemorySize,
                             GEMM_SMEM);
        cudaFuncSetAttribute(flash_mma,
                             cudaFuncAttributeMaxDynamicSharedMemorySize,
                             FLASH_SMEM);
        attr_set = 1;
    }

    dim3 bb(256);
    const size_t XN = (size_t)MROWS * D_MODEL;
    const size_t WN = (size_t)D_MODEL * D_MODEL;

    half_prep<<<dim3(1024, 3), bb>>>(query, key, value, query,
                                     Xh, Xh + XN, Xh + 2*XN, Xh, (int)(XN/4));
    half_prep<<<dim3(512, 4), bb>>>(W_q, W_k, W_v, W_o,
                                    Wh, Wh + WN, Wh + 2*WN, Wh + 3*WN,
                                    (int)(WN/4));

    dim3 gqkv(MROWS/128, D_MODEL/128, 3);
    gemm_mma<<<gqkv, bb, GEMM_SMEM>>>(Xh, Xh + XN, Xh + 2*XN,
                                      Wh, Wh + WN, Wh + 2*WN,
                                      b_q, b_k, b_v,
                                      Qp, Kp, Vp, 1);

    dim3 fg(SEQ/128, BATCH*NHEAD);
    flash_mma<<<fg, bb, FLASH_SMEM>>>(Qp, Kp, Vp, Cp);

    dim3 go(MROWS/128, D_MODEL/128, 1);
    gemm_mma<<<go, bb, GEMM_SMEM>>>(Cp, Cp, Cp,
                                    Wh + 3*WN, Wh + 3*WN, Wh + 3*WN,
                                    b_o, b_o, b_o,
                                    out, out, out, 0);
}

// round 9
// speedup vs baseline: 6.3922x; 1.0477x over previous
#include <cuda_runtime.h>
#include <cuda_fp16.h>
#include <math.h>
#include <stdint.h>

#define D_MODEL 1024
#define NHEAD   16
#define DK      64
#define BATCH   2
#define SEQ     2048
#define MROWS   (BATCH*SEQ)   // 4096

#define QSCALE (0.125f * 1.44269504088896340736f)   // 1/sqrt(dk) * log2(e)

// ---- scratch (device globals; fp16) ----
__device__ __half g_Q[BATCH*NHEAD*SEQ*DK];   // [b][h][s][d], scaled
__device__ __half g_K[BATCH*NHEAD*SEQ*DK];   // [b][h][s][d]
__device__ __half g_V[BATCH*NHEAD*SEQ*DK];   // TRANSPOSED [b][h][d][s]
__device__ __half g_C[MROWS*D_MODEL];        // combined [b][s][h*64+d]
__device__ __half g_Xh[3*MROWS*D_MODEL];     // fp16 query/key/value
__device__ __half g_Wh[4*D_MODEL*D_MODEL];   // fp16 W_q/W_k/W_v/W_o

// ============================================================
// helpers
// ============================================================
__device__ __forceinline__ uint32_t smem_u32(const void* p) {
    uint32_t a;
    asm("{ .reg .u64 t; cvta.to.shared.u64 t, %1; cvt.u32.u64 %0, t; }"
        : "=r"(a) : "l"(p));
    return a;
}
__device__ __forceinline__ float ex2(float x) {
    float r;
    asm("ex2.approx.f32 %0, %1;" : "=f"(r) : "f"(x));
    return r;
}
__device__ __forceinline__ uint32_t pack_h2(float lo, float hi) {
    uint32_t r;
    asm("cvt.rn.f16x2.f32 %0, %1, %2;" : "=r"(r) : "f"(hi), "f"(lo));
    return r;
}
#define CP16(dst, src) \
    asm volatile("cp.async.cg.shared.global [%0], [%1], 16;" \
                 :: "r"(dst), "l"(src) : "memory")
#define CPCOMMIT() asm volatile("cp.async.commit_group;" ::: "memory")
#define CPWAIT0()  asm volatile("cp.async.wait_group 0;" ::: "memory")

__device__ __forceinline__ void ldmx4(uint32_t* r, uint32_t addr) {
    asm volatile("ldmatrix.sync.aligned.m8n8.x4.shared.b16 "
                 "{%0,%1,%2,%3}, [%4];"
                 : "=r"(r[0]), "=r"(r[1]), "=r"(r[2]), "=r"(r[3])
                 : "r"(addr));
}

// D += A*B, m16n8k16 fp16 with f32 accumulate
__device__ __forceinline__ void mma_f16(float* d, const uint32_t* a,
                                        uint32_t b0, uint32_t b1) {
    asm volatile("mma.sync.aligned.m16n8k16.row.col.f32.f16.f16.f32 "
                 "{%0,%1,%2,%3}, {%4,%5,%6,%7}, {%8,%9}, {%0,%1,%2,%3};"
                 : "+f"(d[0]), "+f"(d[1]), "+f"(d[2]), "+f"(d[3])
                 : "r"(a[0]), "r"(a[1]), "r"(a[2]), "r"(a[3]),
                   "r"(b0), "r"(b1));
}

// ============================================================
// prep: f32 -> f16
// ============================================================
__global__ __launch_bounds__(256) void half_prep(
    const float* __restrict__ s0, const float* __restrict__ s1,
    const float* __restrict__ s2, const float* __restrict__ s3,
    __half* __restrict__ d0, __half* __restrict__ d1,
    __half* __restrict__ d2, __half* __restrict__ d3, int n4)
{
    const int z = blockIdx.y;
    const float4* s = (const float4*)((z == 0) ? s0 : (z == 1) ? s1
                                    : (z == 2) ? s2 : s3);
    uint2* d = (uint2*)((z == 0) ? d0 : (z == 1) ? d1 : (z == 2) ? d2 : d3);
    for (int i = blockIdx.x * blockDim.x + threadIdx.x; i < n4;
         i += gridDim.x * blockDim.x) {
        float4 v = s[i];
        d[i] = make_uint2(pack_h2(v.x, v.y), pack_h2(v.z, v.w));
    }
}

// ============================================================
// GEMM fp16 (unchanged from R8): CTA 128x128, BK=64, 8 warps.
// ============================================================
#define GPADH 72
#define GOPB  (128*GPADH*2)            // 18432
#define GSTGB (2*GOPB)
#define GEMM_SMEM (2*GSTGB)            // 73728 B

__global__ __launch_bounds__(256, 2) void gemm_mma(
    const __half* __restrict__ A0, const __half* __restrict__ A1,
    const __half* __restrict__ A2,
    const __half* __restrict__ W0, const __half* __restrict__ W1,
    const __half* __restrict__ W2,
    const float* __restrict__ bias0, const float* __restrict__ bias1,
    const float* __restrict__ bias2,
    void* __restrict__ O0, void* __restrict__ O1, void* __restrict__ O2,
    int split)
{
    extern __shared__ uint32_t su[];
    const uint32_t sbase = smem_u32(su);

    const int z = blockIdx.z;
    const __half* A   = (z == 0) ? A0 : (z == 1) ? A1 : A2;
    const __half* W   = (z == 0) ? W0 : (z == 1) ? W1 : W2;
    const float* bias = (z == 0) ? bias0 : (z == 1) ? bias1 : bias2;
    void* outv        = (z == 0) ? O0 : (z == 1) ? O1 : O2;

    const int tid = threadIdx.x;
    const int w    = tid >> 5;
    const int lane = tid & 31;
    const int g   = lane >> 2;
    const int tig = lane & 3;
    const int wm  = w >> 2;
    const int wn  = w & 3;
    const int m0  = blockIdx.x * 128;
    const int n0  = blockIdx.y * 128;

    const int lr  = tid >> 1;
    const int lc0 = (tid & 1) * 32;
    const __half* Ag = A + (size_t)(m0 + lr) * D_MODEL + lc0;
    const __half* Wg = W + (size_t)(n0 + lr) * D_MODEL + lc0;
    const uint32_t dsm = (uint32_t)(lr*GPADH + lc0) * 2;

    const int row_a = (lane & 7) + (((lane >> 3) & 1) << 3);
    const int col_a = (lane >> 4) << 3;
    const int row_b = (lane & 7) + ((lane >> 4) << 3);
    const int col_b = ((lane >> 3) & 1) << 3;
    const uint32_t a_lm = (uint32_t)((wm*64 + row_a)*GPADH + col_a) * 2;
    const uint32_t b_lm = (uint32_t)(GOPB)
        + (uint32_t)((wn*32 + row_b)*GPADH + col_b) * 2;

    float acc[4][4][4];
    #pragma unroll
    for (int mt = 0; mt < 4; ++mt)
        #pragma unroll
        for (int nt = 0; nt < 4; ++nt)
            #pragma unroll
            for (int q = 0; q < 4; ++q) acc[mt][nt][q] = 0.f;

    #pragma unroll
    for (int i = 0; i < 4; ++i) {
        CP16(sbase + dsm + 16*i, Ag + 8*i);
        CP16(sbase + GOPB + dsm + 16*i, Wg + 8*i);
    }
    CPCOMMIT();

    for (int c = 0; c < 16; ++c) {
        CPWAIT0();
        __syncthreads();
        if (c < 15) {
            const int k0 = (c+1) * 64;
            const uint32_t stg = sbase + (uint32_t)(((c+1) & 1) * GSTGB);
            #pragma unroll
            for (int i = 0; i < 4; ++i) {
                CP16(stg + dsm + 16*i, Ag + k0 + 8*i);
                CP16(stg + GOPB + dsm + 16*i, Wg + k0 + 8*i);
            }
            CPCOMMIT();
        }

        const uint32_t stg = sbase + (uint32_t)((c & 1) * GSTGB);
        #pragma unroll
        for (int ks = 0; ks < 4; ++ks) {
            uint32_t af[4][4];
            #pragma unroll
            for (int mt = 0; mt < 4; ++mt)
                ldmx4(af[mt], stg + a_lm
                      + (uint32_t)(mt*16*GPADH)*2 + ks*32);
            #pragma unroll
            for (int p = 0; p < 2; ++p) {
                uint32_t bf[4];
                ldmx4(bf, stg + b_lm + (uint32_t)(p*16*GPADH)*2 + ks*32);
                #pragma unroll
                for (int mt = 0; mt < 4; ++mt) {
                    mma_f16(acc[mt][2*p],   af[mt], bf[0], bf[1]);
                    mma_f16(acc[mt][2*p+1], af[mt], bf[2], bf[3]);
                }
            }
        }
    }

    const float osc = (split && z == 0) ? QSCALE : 1.0f;
    #pragma unroll
    for (int mt = 0; mt < 4; ++mt) {
        #pragma unroll
        for (int nt = 0; nt < 4; ++nt) {
            const int n  = n0 + wn*32 + nt*8 + 2*tig;
            const float2 bb = *(const float2*)&bias[n];
            const int r0 = m0 + wm*64 + mt*16 + g;
            float2 v0, v1;
            v0.x = acc[mt][nt][0] + bb.x;  v0.y = acc[mt][nt][1] + bb.y;
            v1.x = acc[mt][nt][2] + bb.x;  v1.y = acc[mt][nt][3] + bb.y;
            if (split) {
                __half* out = (__half*)outv;
                const int h = n >> 6, d = n & (DK-1);
                const int b0_ = r0 >> 11, s0_ = r0 & (SEQ-1);
                const int r1 = r0 + 8;
                const int b1_ = r1 >> 11, s1_ = r1 & (SEQ-1);
                if (z == 2) {
                    const size_t h0 = (size_t)(b0_*NHEAD + h) * DK;
                    const size_t h1 = (size_t)(b1_*NHEAD + h) * DK;
                    out[(h0 + d)*SEQ + s0_]     = __float2half_rn(v0.x);
                    out[(h0 + d + 1)*SEQ + s0_] = __float2half_rn(v0.y);
                    out[(h1 + d)*SEQ + s1_]     = __float2half_rn(v1.x);
                    out[(h1 + d + 1)*SEQ + s1_] = __float2half_rn(v1.y);
                } else {
                    uint32_t u0 = pack_h2(v0.x * osc, v0.y * osc);
                    uint32_t u1 = pack_h2(v1.x * osc, v1.y * osc);
                    *(uint32_t*)&out[(((size_t)(b0_*NHEAD + h))*SEQ + s0_)*DK + d] = u0;
                    *(uint32_t*)&out[(((size_t)(b1_*NHEAD + h))*SEQ + s1_)*DK + d] = u1;
                }
            } else {
                float* out = (float*)outv;
                *(float2*)&out[(size_t)r0 * D_MODEL + n] = v0;
                *(float2*)&out[(size_t)(r0+8) * D_MODEL + n] = v1;
            }
        }
    }
}

// ============================================================
// Flash v5: Br=256 (32 rows/warp, 2 m-tiles), Bc=64, Q frags cached
// in registers, fp16 m16n8k16. 1 CTA/SM, 8 warps.
// smem: Q[256][72]h (36864) | stage{0,1}: K[64][72]h+Vt[64][72]h (18432 ea)
// ============================================================
#define FOPB (64*GPADH*2)                  // 9216
#define KVSTGB (2*FOPB)                    // 18432
#define FQB (256*GPADH*2)                  // 36864
#define FLASH_SMEM (FQB + 2*KVSTGB)        // 73728

__global__ __launch_bounds__(256, 1) void flash_mma(
    const __half* __restrict__ Q, const __half* __restrict__ K,
    const __half* __restrict__ Vt, __half* __restrict__ C)
{
    extern __shared__ uint32_t su[];
    const uint32_t sbase = smem_u32(su);

    const int tid = threadIdx.x;
    const int w    = tid >> 5;
    const int lane = tid & 31;
    const int g   = lane >> 2;
    const int tig = lane & 3;
    const int q0  = blockIdx.x * 256;
    const int bh  = blockIdx.y;

    const __half* Qb  = Q + ((size_t)bh*SEQ + q0)*DK;
    const __half* Kb  = K + (size_t)bh*SEQ*DK;
    const __half* Vtb = Vt + (size_t)bh*DK*SEQ;

    // prologue: Q (2048 cp16, 8/thread) + KV stage 0 (2/thread each)
    #pragma unroll
    for (int i = 0; i < 8; ++i) {
        const int fidx = tid + 256*i;
        const int r = fidx >> 3, ch = (fidx & 7) * 8;
        CP16(sbase + (uint32_t)(r*GPADH + ch)*2, Qb + (size_t)r*DK + ch);
    }
    #pragma unroll
    for (int i = 0; i < 2; ++i) {
        const int fidx = tid + 256*i;
        const int r = fidx >> 3, ch = (fidx & 7) * 8;
        CP16(sbase + FQB + (uint32_t)(r*GPADH + ch)*2,
             Kb + (size_t)r*DK + ch);
        CP16(sbase + FQB + FOPB + (uint32_t)(r*GPADH + ch)*2,
             Vtb + (size_t)r*SEQ + ch);
    }
    CPCOMMIT();

    // ldmatrix lane bases
    const int row_a = (lane & 7) + (((lane >> 3) & 1) << 3);
    const int col_a = (lane >> 4) << 3;
    const int row_b = (lane & 7) + ((lane >> 4) << 3);
    const int col_b = ((lane >> 3) & 1) << 3;
    const uint32_t b_lmo = (uint32_t)(row_b*GPADH + col_b)*2;

    CPWAIT0();
    __syncthreads();   // Q + KV0 resident

    // cache Q fragments: 2 m-tiles x 4 k-steps
    uint32_t qa[2][4][4];
    #pragma unroll
    for (int mt = 0; mt < 2; ++mt) {
        const uint32_t q_lm = sbase
            + (uint32_t)((w*32 + mt*16 + row_a)*GPADH + col_a)*2;
        #pragma unroll
        for (int ks = 0; ks < 4; ++ks)
            ldmx4(qa[mt][ks], q_lm + ks*32);
    }

    float mr[2][2], lr[2][2];
    float acc[2][8][4];
    #pragma unroll
    for (int mt = 0; mt < 2; ++mt) {
        mr[mt][0] = -1e30f; mr[mt][1] = -1e30f;
        lr[mt][0] = 0.f;    lr[mt][1] = 0.f;
        #pragma unroll
        for (int nt = 0; nt < 8; ++nt)
            #pragma unroll
            for (int q = 0; q < 4; ++q) acc[mt][nt][q] = 0.f;
    }

    for (int t = 0; t < SEQ/64; ++t) {
        // prefetch t+1 into other buffer (safe: sync at end of t-1
        // ensured all warps finished reading it)
        if (t < SEQ/64 - 1) {
            const uint32_t stg = sbase + FQB + (uint32_t)(((t+1) & 1)*KVSTGB);
            const __half* Kn = Kb + (size_t)(t+1)*64*DK;
            const __half* Vn = Vtb + (size_t)(t+1)*64;
            #pragma unroll
            for (int i = 0; i < 2; ++i) {
                const int fidx = tid + 256*i;
                const int r = fidx >> 3, ch = (fidx & 7) * 8;
                CP16(stg + (uint32_t)(r*GPADH + ch)*2,
                     Kn + (size_t)r*DK + ch);
                CP16(stg + FOPB + (uint32_t)(r*GPADH + ch)*2,
                     Vn + (size_t)r*SEQ + ch);
            }
            CPCOMMIT();
        }

        const uint32_t k_lm = sbase + FQB + (uint32_t)((t & 1)*KVSTGB) + b_lmo;
        const uint32_t v_lm = k_lm + FOPB;

        // ---- S = Q K^T (log2 domain): 2 m-tiles x 8 n-tiles ----
        float s[2][8][4];
        #pragma unroll
        for (int mt = 0; mt < 2; ++mt)
            #pragma unroll
            for (int nt = 0; nt < 8; ++nt)
                #pragma unroll
                for (int q = 0; q < 4; ++q) s[mt][nt][q] = 0.f;
        #pragma unroll
        for (int ks = 0; ks < 4; ++ks) {
            #pragma unroll
            for (int p = 0; p < 4; ++p) {
                uint32_t kf[4];
                ldmx4(kf, k_lm + (uint32_t)(p*16*GPADH)*2 + ks*32);
                #pragma unroll
                for (int mt = 0; mt < 2; ++mt) {
                    mma_f16(s[mt][2*p],   qa[mt][ks], kf[0], kf[1]);
                    mma_f16(s[mt][2*p+1], qa[mt][ks], kf[2], kf[3]);
                }
            }
        }

        // ---- warp-local online softmax (base 2), per m-tile ----
        #pragma unroll
        for (int mt = 0; mt < 2; ++mt) {
            float mx0 = -1e30f, mx1 = -1e30f;
            #pragma unroll
            for (int nt = 0; nt < 8; ++nt) {
                mx0 = fmaxf(mx0, fmaxf(s[mt][nt][0], s[mt][nt][1]));
                mx1 = fmaxf(mx1, fmaxf(s[mt][nt][2], s[mt][nt][3]));
            }
            mx0 = fmaxf(mx0, __shfl_xor_sync(0xffffffffu, mx0, 1));
            mx0 = fmaxf(mx0, __shfl_xor_sync(0xffffffffu, mx0, 2));
            mx1 = fmaxf(mx1, __shfl_xor_sync(0xffffffffu, mx1, 1));
            mx1 = fmaxf(mx1, __shfl_xor_sync(0xffffffffu, mx1, 2));
            const float mn0 = fmaxf(mr[mt][0], mx0);
            const float mn1 = fmaxf(mr[mt][1], mx1);
            const float cr0 = ex2(mr[mt][0] - mn0);
            const float cr1 = ex2(mr[mt][1] - mn1);

            float sum0 = 0.f, sum1 = 0.f;
            #pragma unroll
            for (int nt = 0; nt < 8; ++nt) {
                s[mt][nt][0] = ex2(s[mt][nt][0] - mn0);
                s[mt][nt][1] = ex2(s[mt][nt][1] - mn0);
                s[mt][nt][2] = ex2(s[mt][nt][2] - mn1);
                s[mt][nt][3] = ex2(s[mt][nt][3] - mn1);
                sum0 += s[mt][nt][0] + s[mt][nt][1];
                sum1 += s[mt][nt][2] + s[mt][nt][3];
            }
            sum0 += __shfl_xor_sync(0xffffffffu, sum0, 1);
            sum0 += __shfl_xor_sync(0xffffffffu, sum0, 2);
            sum1 += __shfl_xor_sync(0xffffffffu, sum1, 1);
            sum1 += __shfl_xor_sync(0xffffffffu, sum1, 2);
            lr[mt][0] = lr[mt][0] * cr0 + sum0;
            lr[mt][1] = lr[mt][1] * cr1 + sum1;
            mr[mt][0] = mn0;  mr[mt][1] = mn1;

            #pragma unroll
            for (int nt = 0; nt < 8; ++nt) {
                acc[mt][nt][0] *= cr0;  acc[mt][nt][1] *= cr0;
                acc[mt][nt][2] *= cr1;  acc[mt][nt][3] *= cr1;
            }
        }

        // ---- O += P V ----
        #pragma unroll
        for (int j = 0; j < 4; ++j) {
            uint32_t a[2][4];
            #pragma unroll
            for (int mt = 0; mt < 2; ++mt) {
                a[mt][0] = pack_h2(s[mt][2*j][0],   s[mt][2*j][1]);
                a[mt][1] = pack_h2(s[mt][2*j][2],   s[mt][2*j][3]);
                a[mt][2] = pack_h2(s[mt][2*j+1][0], s[mt][2*j+1][1]);
                a[mt][3] = pack_h2(s[mt][2*j+1][2], s[mt][2*j+1][3]);
            }
            #pragma unroll
            for (int p = 0; p < 4; ++p) {
                uint32_t vf[4];
                ldmx4(vf, v_lm + (uint32_t)(p*16*GPADH)*2 + j*32);
                #pragma unroll
                for (int mt = 0; mt < 2; ++mt) {
                    mma_f16(acc[mt][2*p],   a[mt], vf[0], vf[1]);
                    mma_f16(acc[mt][2*p+1], a[mt], vf[2], vf[3]);
                }
            }
        }

        if (t < SEQ/64 - 1) {
            CPWAIT0();
            __syncthreads();
        }
    }

    // epilogue
    const int b = bh >> 4;
    const int h = bh & 15;
    #pragma unroll
    for (int mt = 0; mt < 2; ++mt) {
        const float inv0 = 1.f / lr[mt][0];
        const float inv1 = 1.f / lr[mt][1];
        const int r0g = q0 + w*32 + mt*16 + g;
        #pragma unroll
        for (int nt = 0; nt < 8; ++nt) {
            const int col = h*DK + nt*8 + 2*tig;
            uint32_t u0 = pack_h2(acc[mt][nt][0] * inv0, acc[mt][nt][1] * inv0);
            uint32_t u1 = pack_h2(acc[mt][nt][2] * inv1, acc[mt][nt][3] * inv1);
            *(uint32_t*)&C[((size_t)(b*SEQ + r0g))*D_MODEL + col] = u0;
            *(uint32_t*)&C[((size_t)(b*SEQ + r0g + 8))*D_MODEL + col] = u1;
        }
    }
}

// ============================================================
// Launch
// ============================================================
extern "C" void kernel_launch(void* const* d_in, const int* in_sizes, int n_in,
                              void* d_out, int out_size)
{
    const float* query = (const float*)d_in[0];
    const float* key   = (const float*)d_in[1];
    const float* value = (const float*)d_in[2];
    const float* W_q   = (const float*)d_in[3];
    const float* b_q   = (const float*)d_in[4];
    const float* W_k   = (const float*)d_in[5];
    const float* b_k   = (const float*)d_in[6];
    const float* W_v   = (const float*)d_in[7];
    const float* b_v   = (const float*)d_in[8];
    const float* W_o   = (const float*)d_in[9];
    const float* b_o   = (const float*)d_in[10];
    float* out = (float*)d_out;

    __half *Qp, *Kp, *Vp, *Cp, *Xh, *Wh;
    cudaGetSymbolAddress((void**)&Qp, g_Q);
    cudaGetSymbolAddress((void**)&Kp, g_K);
    cudaGetSymbolAddress((void**)&Vp, g_V);
    cudaGetSymbolAddress((void**)&Cp, g_C);
    cudaGetSymbolAddress((void**)&Xh, g_Xh);
    cudaGetSymbolAddress((void**)&Wh, g_Wh);

    static int attr_set = 0;
    if (!attr_set) {
        cudaFuncSetAttribute(gemm_mma,
                             cudaFuncAttributeMaxDynamicSharedMemorySize,
                             GEMM_SMEM);
        cudaFuncSetAttribute(flash_mma,
                             cudaFuncAttributeMaxDynamicSharedMemorySize,
                             FLASH_SMEM);
        attr_set = 1;
    }

    dim3 bb(256);
    const size_t XN = (size_t)MROWS * D_MODEL;
    const size_t WN = (size_t)D_MODEL * D_MODEL;

    half_prep<<<dim3(1024, 3), bb>>>(query, key, value, query,
                                     Xh, Xh + XN, Xh + 2*XN, Xh, (int)(XN/4));
    half_prep<<<dim3(512, 4), bb>>>(W_q, W_k, W_v, W_o,
                                    Wh, Wh + WN, Wh + 2*WN, Wh + 3*WN,
                                    (int)(WN/4));

    dim3 gqkv(MROWS/128, D_MODEL/128, 3);
    gemm_mma<<<gqkv, bb, GEMM_SMEM>>>(Xh, Xh + XN, Xh + 2*XN,
                                      Wh, Wh + WN, Wh + 2*WN,
                                      b_q, b_k, b_v,
                                      Qp, Kp, Vp, 1);

    dim3 fg(SEQ/256, BATCH*NHEAD);     // (8, 32)
    flash_mma<<<fg, bb, FLASH_SMEM>>>(Qp, Kp, Vp, Cp);

    dim3 go(MROWS/128, D_MODEL/128, 1);
    gemm_mma<<<go, bb, GEMM_SMEM>>>(Cp, Cp, Cp,
                                    Wh + 3*WN, Wh + 3*WN, Wh + 3*WN,
                                    b_o, b_o, b_o,
                                    out, out, out, 0);
}